// round 13
// baseline (speedup 1.0000x reference)
#include <cuda_runtime.h>
#include <cuda_bf16.h>
#include <cstdint>

// Problem constants
constexpr int Nn = 50000;
constexpr int D  = 128;
constexpr int E  = 800000;
constexpr int SCAN_B = 512;
constexpr int SCAN_G = (Nn + SCAN_B - 1) / SCAN_B;   // 98

// Scratch (static device globals)
__device__ float g_aggr[(size_t)Nn * D];   // holds h = x + aggr
__device__ float g_t[(size_t)Nn * D];
__device__ float g_stats[2 * D];
__device__ int   g_cnt[Nn];
__device__ int   g_start[Nn];
__device__ int   g_cur[Nn];
__device__ int   g_desc[SCAN_G];           // decoupled-lookback descriptors
__device__ int   g_bar;                    // software grid barrier counter
__device__ uint2 g_perm[E];                // (edge_id, src), sorted by dst
// W1/W2 split bf16 hi/lo, fragment-major for m16n8k16 B-operand
__device__ uint32_t g_Bh[2][8192];
__device__ uint32_t g_Bl[2][8192];

// ---------------------------------------------------------------------------
// init: blocks 0-1 pack W1/W2 (bf16 hi/lo fragment-major); blocks 2+ zero
// g_cnt / g_stats / g_desc / g_bar.
// ---------------------------------------------------------------------------
__global__ void init_kernel(const float* __restrict__ W1, const float* __restrict__ W2) {
    if (blockIdx.x < 2) {
        const float* W = blockIdx.x ? W2 : W1;
        uint32_t* bh = g_Bh[blockIdx.x];
        uint32_t* bl = g_Bl[blockIdx.x];
        for (int i = threadIdx.x; i < 64 * 128; i += blockDim.x) {
            int k2 = i >> 7, c = i & 127, k = k2 * 2;
            float w0 = __ldg(W + (size_t)k * D + c);
            float w1 = __ldg(W + (size_t)(k + 1) * D + c);
            __nv_bfloat16 h0 = __float2bfloat16(w0);
            __nv_bfloat16 h1 = __float2bfloat16(w1);
            __nv_bfloat16 l0 = __float2bfloat16(w0 - __bfloat162float(h0));
            __nv_bfloat16 l1 = __float2bfloat16(w1 - __bfloat162float(h1));
            int kstep = k2 >> 3;
            int n16   = c >> 4;
            int lane  = (c & 7) * 4 + (k2 & 3);
            int slot  = 2 * ((c >> 3) & 1) + ((k2 >> 2) & 1);
            int idx   = ((kstep * 8 + n16) * 32 + lane) * 4 + slot;
            bh[idx] = (uint32_t)__bfloat16_as_ushort(h0) | ((uint32_t)__bfloat16_as_ushort(h1) << 16);
            bl[idx] = (uint32_t)__bfloat16_as_ushort(l0) | ((uint32_t)__bfloat16_as_ushort(l1) << 16);
        }
    } else {
        int i = (blockIdx.x - 2) * blockDim.x + threadIdx.x;
        if (i < Nn) g_cnt[i] = 0;
        if (i < 2 * D) g_stats[i] = 0.f;
        if (i < SCAN_G) g_desc[i] = 0;
        if (i == 0) g_bar = 0;
    }
}

// ---------------------------------------------------------------------------
// build: histogram (grid-stride, int4) -> software grid barrier -> exclusive
// scan via decoupled lookback. 98 blocks <= 148 SMs: all co-resident in wave
// 1, so both the barrier and the lookback are deadlock-free.
// ---------------------------------------------------------------------------
__global__ __launch_bounds__(SCAN_B)
void build_kernel(const int* __restrict__ ei) {
    const int b = blockIdx.x;
    const int t = threadIdx.x;

    // -- phase 1: histogram of dst --
    {
        const int4* d4p = reinterpret_cast<const int4*>(ei + E);
        int gid = b * SCAN_B + t;
        for (int v = gid; v < E / 4; v += SCAN_G * SCAN_B) {
            int4 d4 = __ldg(d4p + v);
            atomicAdd(&g_cnt[d4.x], 1);
            atomicAdd(&g_cnt[d4.y], 1);
            atomicAdd(&g_cnt[d4.z], 1);
            atomicAdd(&g_cnt[d4.w], 1);
        }
    }
    __syncthreads();
    if (t == 0) {
        atomicAdd(&g_bar, 1);
        while (atomicAdd(&g_bar, 0) < SCAN_G) __nanosleep(64);
    }
    __syncthreads();

    // -- phase 2: exclusive scan (decoupled lookback) --
    __shared__ int sm[SCAN_B];
    __shared__ int s_prefix;
    int i = b * SCAN_B + t;
    int v = (i < Nn) ? __ldcg(&g_cnt[i]) : 0;
    sm[t] = v;
    __syncthreads();
#pragma unroll
    for (int off = 1; off < SCAN_B; off <<= 1) {
        int tmp = (t >= off) ? sm[t - off] : 0;
        __syncthreads();
        sm[t] += tmp;
        __syncthreads();
    }
    int total = sm[SCAN_B - 1];

    if (b == 0) {
        if (t == 0) {
            atomicExch(&g_desc[0], (total << 2) | 2);
            s_prefix = 0;
        }
    } else {
        if (t == 0) atomicExch(&g_desc[b], (total << 2) | 1);
        if (t < 32) {
            int prefix = 0, offset = 0;
            bool done = false;
            while (!done) {
                int j = b - 1 - offset - t;
                int d;
                if (j >= 0) {
                    do { d = atomicAdd(&g_desc[j], 0); } while ((d & 3) == 0);
                } else {
                    d = 2;
                }
                unsigned mask = __ballot_sync(0xffffffffu, (d & 3) == 2);
                int contrib;
                if (mask) {
                    int firstP = __ffs(mask) - 1;
                    contrib = (t <= firstP) ? (d >> 2) : 0;
                    done = true;
                } else {
                    contrib = d >> 2;
                }
#pragma unroll
                for (int o = 16; o; o >>= 1) contrib += __shfl_xor_sync(0xffffffffu, contrib, o);
                prefix += contrib;
                offset += 32;
            }
            if (t == 0) {
                atomicExch(&g_desc[b], ((prefix + total) << 2) | 2);
                s_prefix = prefix;
            }
        }
    }
    __syncthreads();
    int s = sm[t] - v + s_prefix;
    if (i < Nn) { g_start[i] = s; g_cur[i] = s; }
}

// ---------------------------------------------------------------------------
// Scatter: 4 edges/thread (int4 loads) -> 4 independent atomic+store chains
// in flight per thread (was 1).
// ---------------------------------------------------------------------------
__global__ void scatter_kernel(const int* __restrict__ ei) {
    int v = blockIdx.x * blockDim.x + threadIdx.x;
    if (v >= E / 4) return;
    int4 s4 = __ldg(reinterpret_cast<const int4*>(ei) + v);
    int4 d4 = __ldg(reinterpret_cast<const int4*>(ei + E) + v);
    int e0 = v * 4;
    int p0 = atomicAdd(&g_cur[d4.x], 1);
    int p1 = atomicAdd(&g_cur[d4.y], 1);
    int p2 = atomicAdd(&g_cur[d4.z], 1);
    int p3 = atomicAdd(&g_cur[d4.w], 1);
    g_perm[p0] = make_uint2((unsigned)(e0),     (unsigned)s4.x);
    g_perm[p1] = make_uint2((unsigned)(e0 + 1), (unsigned)s4.y);
    g_perm[p2] = make_uint2((unsigned)(e0 + 2), (unsigned)s4.z);
    g_perm[p3] = make_uint2((unsigned)(e0 + 3), (unsigned)s4.w);
}

// ---------------------------------------------------------------------------
// Aggregate: one warp per node. acc = x[i] + sum relu(x[src] + ea[e]).
// ea via __ldcs (evict-first streaming) so the 410MB read-once stream does
// not thrash the 25.6MB x working set out of L2. Identical to 206.9us ver.
// ---------------------------------------------------------------------------
__global__ __launch_bounds__(256)
void aggregate_kernel(const float* __restrict__ x, const float* __restrict__ ea) {
    int node = (int)(((size_t)blockIdx.x * blockDim.x + threadIdx.x) >> 5);
    int lane = threadIdx.x & 31;
    if (node >= Nn) return;
    const float4* x4  = reinterpret_cast<const float4*>(x);
    const float4* ea4 = reinterpret_cast<const float4*>(ea);
    float4 acc = __ldg(x4 + (size_t)node * 32 + lane);   // seed with x_i
    int start = g_start[node];
    int cnt   = g_cnt[node];
    for (int base = 0; base < cnt; base += 32) {
        int m = cnt - base; if (m > 32) m = 32;
        uint2 p = make_uint2(0u, 0u);
        if (lane < m) p = __ldg(g_perm + start + base + lane);
        for (int j = 0; j < m; j += 4) {
#pragma unroll
            for (int u = 0; u < 4; u++) {
                if (j + u < m) {
                    uint32_t e = __shfl_sync(0xffffffffu, p.x, j + u);
                    uint32_t s = __shfl_sync(0xffffffffu, p.y, j + u);
                    float4 xv = __ldg(x4 + (size_t)s * 32 + lane);     // L2-resident
                    float4 ev = __ldcs(ea4 + (size_t)e * 32 + lane);   // streaming
                    acc.x += fmaxf(xv.x + ev.x, 0.f);
                    acc.y += fmaxf(xv.y + ev.y, 0.f);
                    acc.z += fmaxf(xv.z + ev.z, 0.f);
                    acc.w += fmaxf(xv.w + ev.w, 0.f);
                }
            }
        }
    }
    *(reinterpret_cast<float4*>(g_aggr) + (size_t)node * 32 + lane) = acc;
}

// ---------------------------------------------------------------------------
// Tensor-core MLP, 64x128x128 tile per block, 256 threads (8 warps, 2x4 grid),
// 97 KB smem -> 2 blocks/SM. Identical to 206.9us version.
//   mode 0: A = g_aggr (= x+aggr); g_t = relu(A@W1 + b1)
//   mode 1: A = g_t;               out = x + A@W2 + b2  (+ BN column stats)
// ---------------------------------------------------------------------------
#define MMA_BF16(d, av, b0, b1) \
    asm volatile("mma.sync.aligned.m16n8k16.row.col.f32.bf16.bf16.f32 " \
                 "{%0,%1,%2,%3},{%4,%5,%6,%7},{%8,%9},{%0,%1,%2,%3};" \
                 : "+f"((d)[0]), "+f"((d)[1]), "+f"((d)[2]), "+f"((d)[3]) \
                 : "r"((av).x), "r"((av).y), "r"((av).z), "r"((av).w), \
                   "r"(b0), "r"(b1))

__global__ __launch_bounds__(256, 2)
void mlp_tc(const float* __restrict__ x, const float* __restrict__ bias,
            float* __restrict__ out, int mode) {
    extern __shared__ __align__(16) unsigned char smem[];
    uint32_t* Ah = reinterpret_cast<uint32_t*>(smem);   // [4096]
    uint32_t* Al = Ah + 4096;                           // [4096]
    uint32_t* Bh = Al + 4096;                           // [8192]
    uint32_t* Bl = Bh + 8192;                           // [8192]
    float* cs = reinterpret_cast<float*>(Bl + 8192);    // [128]
    float* cq = cs + 128;
    const int tid = threadIdx.x, wid = tid >> 5, lane = tid & 31;
    const int r0 = blockIdx.x * 64;

    {
        const uint4* sh = reinterpret_cast<const uint4*>(g_Bh[mode]);
        const uint4* sl = reinterpret_cast<const uint4*>(g_Bl[mode]);
        uint4* dh = reinterpret_cast<uint4*>(Bh);
        uint4* dl = reinterpret_cast<uint4*>(Bl);
#pragma unroll
        for (int i = tid; i < 2048; i += 256) { dh[i] = __ldg(sh + i); dl[i] = __ldg(sl + i); }
    }

#pragma unroll
    for (int i = tid; i < 2048; i += 256) {
        int r = i >> 5, q = i & 31;
        int gr = r0 + r;
        float4 a = make_float4(0.f, 0.f, 0.f, 0.f);
        if (gr < Nn) {
            const float* src = mode == 0 ? g_aggr : g_t;
            a = *(reinterpret_cast<const float4*>(src) + (size_t)gr * 32 + q);
        }
        __nv_bfloat16 h0 = __float2bfloat16(a.x), h1 = __float2bfloat16(a.y);
        __nv_bfloat16 h2 = __float2bfloat16(a.z), h3 = __float2bfloat16(a.w);
        __nv_bfloat16 l0 = __float2bfloat16(a.x - __bfloat162float(h0));
        __nv_bfloat16 l1 = __float2bfloat16(a.y - __bfloat162float(h1));
        __nv_bfloat16 l2 = __float2bfloat16(a.z - __bfloat162float(h2));
        __nv_bfloat16 l3 = __float2bfloat16(a.w - __bfloat162float(h3));
        uint32_t hp0 = (uint32_t)__bfloat16_as_ushort(h0) | ((uint32_t)__bfloat16_as_ushort(h1) << 16);
        uint32_t hp1 = (uint32_t)__bfloat16_as_ushort(h2) | ((uint32_t)__bfloat16_as_ushort(h3) << 16);
        uint32_t lp0 = (uint32_t)__bfloat16_as_ushort(l0) | ((uint32_t)__bfloat16_as_ushort(l1) << 16);
        uint32_t lp1 = (uint32_t)__bfloat16_as_ushort(l2) | ((uint32_t)__bfloat16_as_ushort(l3) << 16);
        int kstep = q >> 2;
        int m16   = r >> 4;
        int l     = (r & 7) * 4 + (q & 1) * 2;
        int s     = ((r >> 3) & 1) + 2 * ((q >> 1) & 1);
        int base  = (kstep * 4 + m16) * 32;
        int i0 = (base + ((l)     ^ kstep)) * 4 + s;
        int i1 = (base + ((l + 1) ^ kstep)) * 4 + s;
        Ah[i0] = hp0; Ah[i1] = hp1;
        Al[i0] = lp0; Al[i1] = lp1;
    }
    if (tid < 128) { cs[tid] = 0.f; cq[tid] = 0.f; }
    __syncthreads();

    const int wm = wid & 1, wn = wid >> 1;   // 2x4 warp grid, 32x32 per warp
    float acc[2][2][2][4];
#pragma unroll
    for (int im = 0; im < 2; im++)
#pragma unroll
        for (int in = 0; in < 2; in++)
#pragma unroll
            for (int j = 0; j < 2; j++)
#pragma unroll
                for (int v = 0; v < 4; v++) acc[im][in][j][v] = 0.f;

#pragma unroll
    for (int ks = 0; ks < 8; ks++) {
        uint4 ahv[2], alv[2], bhv[2], blv[2];
#pragma unroll
        for (int im = 0; im < 2; im++) {
            int idx = ((ks * 4 + wm * 2 + im) * 32 + (lane ^ ks)) * 4;
            ahv[im] = *reinterpret_cast<const uint4*>(Ah + idx);
            alv[im] = *reinterpret_cast<const uint4*>(Al + idx);
        }
#pragma unroll
        for (int in = 0; in < 2; in++) {
            int idx = ((ks * 8 + wn * 2 + in) * 32 + lane) * 4;
            bhv[in] = *reinterpret_cast<const uint4*>(Bh + idx);
            blv[in] = *reinterpret_cast<const uint4*>(Bl + idx);
        }
#pragma unroll
        for (int im = 0; im < 2; im++)
#pragma unroll
            for (int in = 0; in < 2; in++)
#pragma unroll
                for (int j = 0; j < 2; j++) {
                    uint32_t b0h = j ? bhv[in].z : bhv[in].x;
                    uint32_t b1h = j ? bhv[in].w : bhv[in].y;
                    uint32_t b0l = j ? blv[in].z : blv[in].x;
                    uint32_t b1l = j ? blv[in].w : blv[in].y;
                    MMA_BF16(acc[im][in][j], ahv[im], b0h, b1h);
                    MMA_BF16(acc[im][in][j], ahv[im], b0l, b1l);
                    MMA_BF16(acc[im][in][j], alv[im], b0h, b1h);
                }
    }

    const int tg = lane >> 2, tc = lane & 3;
    float2 bv[2][2];
#pragma unroll
    for (int in = 0; in < 2; in++)
#pragma unroll
        for (int j = 0; j < 2; j++)
            bv[in][j] = __ldg(reinterpret_cast<const float2*>(bias + wn * 32 + in * 16 + j * 8 + tc * 2));

    if (mode == 0) {
#pragma unroll
        for (int im = 0; im < 2; im++)
#pragma unroll
            for (int rh = 0; rh < 2; rh++) {
                int gr = r0 + (wm * 2 + im) * 16 + rh * 8 + tg;
                if (gr < Nn) {
                    float* op = g_t + (size_t)gr * D;
#pragma unroll
                    for (int in = 0; in < 2; in++)
#pragma unroll
                        for (int j = 0; j < 2; j++) {
                            int col = wn * 32 + in * 16 + j * 8 + tc * 2;
                            float2 v;
                            v.x = fmaxf(acc[im][in][j][rh * 2]     + bv[in][j].x, 0.f);
                            v.y = fmaxf(acc[im][in][j][rh * 2 + 1] + bv[in][j].y, 0.f);
                            *reinterpret_cast<float2*>(op + col) = v;
                        }
                }
            }
    } else {
        float s8[8], q8[8];
#pragma unroll
        for (int u = 0; u < 8; u++) { s8[u] = 0.f; q8[u] = 0.f; }
#pragma unroll
        for (int im = 0; im < 2; im++)
#pragma unroll
            for (int rh = 0; rh < 2; rh++) {
                int gr = r0 + (wm * 2 + im) * 16 + rh * 8 + tg;
                if (gr < Nn) {
                    const float* xr = x + (size_t)gr * D;
                    float* op = out + (size_t)gr * D;
#pragma unroll
                    for (int in = 0; in < 2; in++)
#pragma unroll
                        for (int j = 0; j < 2; j++) {
                            int col = wn * 32 + in * 16 + j * 8 + tc * 2;
                            float2 xv = __ldg(reinterpret_cast<const float2*>(xr + col));
                            float v0 = acc[im][in][j][rh * 2]     + bv[in][j].x + xv.x;
                            float v1 = acc[im][in][j][rh * 2 + 1] + bv[in][j].y + xv.y;
                            int ci = in * 4 + j * 2;
                            s8[ci] += v0;     q8[ci] += v0 * v0;
                            s8[ci + 1] += v1; q8[ci + 1] += v1 * v1;
                            *reinterpret_cast<float2*>(op + col) = make_float2(v0, v1);
                        }
                }
            }
#pragma unroll
        for (int in = 0; in < 2; in++)
#pragma unroll
            for (int j = 0; j < 2; j++)
#pragma unroll
                for (int h = 0; h < 2; h++) {
                    int col = wn * 32 + in * 16 + j * 8 + tc * 2 + h;
                    int ci = in * 4 + j * 2 + h;
                    atomicAdd(&cs[col], s8[ci]);
                    atomicAdd(&cq[col], q8[ci]);
                }
        __syncthreads();
        if (tid < 128) {
            atomicAdd(&g_stats[tid],     cs[tid]);
            atomicAdd(&g_stats[D + tid], cq[tid]);
        }
    }
}

// ---------------------------------------------------------------------------
// BN: per-block recompute of scale/shift from stats, then in-place apply.
// ---------------------------------------------------------------------------
__global__ void bn_kernel(float* __restrict__ out,
                          const float* __restrict__ bn_w,
                          const float* __restrict__ bn_b) {
    __shared__ float sc_s[D], sh_s[D];
    int tid = threadIdx.x;
    if (tid < D) {
        float inv_n = 1.f / (float)Nn;
        float mean  = g_stats[tid] * inv_n;
        float var   = g_stats[D + tid] * inv_n - mean * mean;
        float rstd  = rsqrtf(var + 1e-5f);
        float sc    = rstd * __ldg(bn_w + tid);
        sc_s[tid] = sc;
        sh_s[tid] = __ldg(bn_b + tid) - mean * sc;
    }
    __syncthreads();
    size_t stride = (size_t)gridDim.x * blockDim.x;
    size_t total  = (size_t)Nn * 32;
    for (size_t v = (size_t)blockIdx.x * blockDim.x + tid; v < total; v += stride) {
        int q = (int)(v & 31);
        float4 h = reinterpret_cast<float4*>(out)[v];
        float4 sc = *reinterpret_cast<const float4*>(sc_s + q * 4);
        float4 sh = *reinterpret_cast<const float4*>(sh_s + q * 4);
        h.x = h.x * sc.x + sh.x;
        h.y = h.y * sc.y + sh.y;
        h.z = h.z * sc.z + sh.z;
        h.w = h.w * sc.w + sh.w;
        reinterpret_cast<float4*>(out)[v] = h;
    }
}

// ---------------------------------------------------------------------------
extern "C" void kernel_launch(void* const* d_in, const int* in_sizes, int n_in,
                              void* d_out, int out_size) {
    const float* x   = (const float*)d_in[0];
    const int*   ei  = (const int*)d_in[1];
    const float* ea  = (const float*)d_in[2];
    const float* W1  = (const float*)d_in[3];
    const float* b1  = (const float*)d_in[4];
    const float* W2  = (const float*)d_in[5];
    const float* b2  = (const float*)d_in[6];
    const float* bnw = (const float*)d_in[7];
    const float* bnb = (const float*)d_in[8];
    float* out = (float*)d_out;

    init_kernel<<<2 + (Nn + 255) / 256, 256>>>(W1, W2);      // (1)
    build_kernel<<<SCAN_G, SCAN_B>>>(ei);                    // (2) hist+scan
    scatter_kernel<<<(E / 4 + 255) / 256, 256>>>(ei);        // (3)
    aggregate_kernel<<<(Nn * 32 + 255) / 256, 256>>>(x, ea); // (4) <- ncu window

    int smem_bytes = (4096 * 2 + 8192 * 2 + 256) * 4;        // 99,328 B
    cudaFuncSetAttribute(mlp_tc, cudaFuncAttributeMaxDynamicSharedMemorySize, smem_bytes);
    int grid = (Nn + 63) / 64;
    mlp_tc<<<grid, 256, smem_bytes>>>(x, b1, nullptr, 0);    // (5)
    mlp_tc<<<grid, 256, smem_bytes>>>(x, b2, out, 1);        // (6)

    bn_kernel<<<1024, 256>>>(out, bnw, bnb);                 // (7)
}

// round 14
// speedup vs baseline: 1.0167x; 1.0167x over previous
#include <cuda_runtime.h>
#include <cuda_bf16.h>
#include <cstdint>

// Problem constants
constexpr int Nn = 50000;
constexpr int D  = 128;
constexpr int E  = 800000;
constexpr int SCAN_B = 512;
constexpr int SCAN_G = (Nn + SCAN_B - 1) / SCAN_B;   // 98

// Scratch (static device globals)
__device__ float g_aggr[(size_t)Nn * D];   // holds h = x + aggr
__device__ float g_t[(size_t)Nn * D];
__device__ float g_stats[2 * D];
__device__ int   g_cnt[Nn];
__device__ int   g_start[Nn];
__device__ int   g_cur[Nn];
__device__ int   g_desc[SCAN_G];           // decoupled-lookback descriptors
__device__ uint2 g_perm[E];                // (edge_id, src), sorted by dst
// W1/W2 split bf16 hi/lo, fragment-major for m16n8k16 B-operand
__device__ uint32_t g_Bh[2][8192];
__device__ uint32_t g_Bl[2][8192];

// ---------------------------------------------------------------------------
// init: blocks 0-1 pack W1/W2 (bf16 hi/lo fragment-major); blocks 2+ zero
// g_cnt / g_stats / g_desc.
// ---------------------------------------------------------------------------
__global__ void init_kernel(const float* __restrict__ W1, const float* __restrict__ W2) {
    if (blockIdx.x < 2) {
        const float* W = blockIdx.x ? W2 : W1;
        uint32_t* bh = g_Bh[blockIdx.x];
        uint32_t* bl = g_Bl[blockIdx.x];
        for (int i = threadIdx.x; i < 64 * 128; i += blockDim.x) {
            int k2 = i >> 7, c = i & 127, k = k2 * 2;
            float w0 = __ldg(W + (size_t)k * D + c);
            float w1 = __ldg(W + (size_t)(k + 1) * D + c);
            __nv_bfloat16 h0 = __float2bfloat16(w0);
            __nv_bfloat16 h1 = __float2bfloat16(w1);
            __nv_bfloat16 l0 = __float2bfloat16(w0 - __bfloat162float(h0));
            __nv_bfloat16 l1 = __float2bfloat16(w1 - __bfloat162float(h1));
            int kstep = k2 >> 3;
            int n16   = c >> 4;
            int lane  = (c & 7) * 4 + (k2 & 3);
            int slot  = 2 * ((c >> 3) & 1) + ((k2 >> 2) & 1);
            int idx   = ((kstep * 8 + n16) * 32 + lane) * 4 + slot;
            bh[idx] = (uint32_t)__bfloat16_as_ushort(h0) | ((uint32_t)__bfloat16_as_ushort(h1) << 16);
            bl[idx] = (uint32_t)__bfloat16_as_ushort(l0) | ((uint32_t)__bfloat16_as_ushort(l1) << 16);
        }
    } else {
        int i = (blockIdx.x - 2) * blockDim.x + threadIdx.x;
        if (i < Nn) g_cnt[i] = 0;
        if (i < 2 * D) g_stats[i] = 0.f;
        if (i < SCAN_G) g_desc[i] = 0;
    }
}

// ---------------------------------------------------------------------------
// Histogram of dst, 4 edges/thread (int4).
// ---------------------------------------------------------------------------
__global__ void hist_kernel(const int* __restrict__ ei) {
    int v = blockIdx.x * blockDim.x + threadIdx.x;
    if (v < E / 4) {
        int4 d4 = __ldg(reinterpret_cast<const int4*>(ei + E) + v);
        atomicAdd(&g_cnt[d4.x], 1);
        atomicAdd(&g_cnt[d4.y], 1);
        atomicAdd(&g_cnt[d4.z], 1);
        atomicAdd(&g_cnt[d4.w], 1);
    }
}

// ---------------------------------------------------------------------------
// Single-kernel exclusive scan over g_cnt via decoupled lookback (R12 ver).
// ---------------------------------------------------------------------------
__global__ __launch_bounds__(SCAN_B)
void scan_kernel() {
    __shared__ int sm[SCAN_B];
    __shared__ int s_prefix;
    const int b = blockIdx.x;
    const int t = threadIdx.x;
    int i = b * SCAN_B + t;
    int v = (i < Nn) ? g_cnt[i] : 0;
    sm[t] = v;
    __syncthreads();
#pragma unroll
    for (int off = 1; off < SCAN_B; off <<= 1) {
        int tmp = (t >= off) ? sm[t - off] : 0;
        __syncthreads();
        sm[t] += tmp;
        __syncthreads();
    }
    int total = sm[SCAN_B - 1];

    if (b == 0) {
        if (t == 0) {
            atomicExch(&g_desc[0], (total << 2) | 2);
            s_prefix = 0;
        }
    } else {
        if (t == 0) atomicExch(&g_desc[b], (total << 2) | 1);
        if (t < 32) {
            int prefix = 0, offset = 0;
            bool done = false;
            while (!done) {
                int j = b - 1 - offset - t;
                int d;
                if (j >= 0) {
                    do { d = atomicAdd(&g_desc[j], 0); } while ((d & 3) == 0);
                } else {
                    d = 2;
                }
                unsigned mask = __ballot_sync(0xffffffffu, (d & 3) == 2);
                int contrib;
                if (mask) {
                    int firstP = __ffs(mask) - 1;
                    contrib = (t <= firstP) ? (d >> 2) : 0;
                    done = true;
                } else {
                    contrib = d >> 2;
                }
#pragma unroll
                for (int o = 16; o; o >>= 1) contrib += __shfl_xor_sync(0xffffffffu, contrib, o);
                prefix += contrib;
                offset += 32;
            }
            if (t == 0) {
                atomicExch(&g_desc[b], ((prefix + total) << 2) | 2);
                s_prefix = prefix;
            }
        }
    }
    __syncthreads();
    int s = sm[t] - v + s_prefix;
    if (i < Nn) { g_start[i] = s; g_cur[i] = s; }
}

// ---------------------------------------------------------------------------
// Scatter: 4 edges/thread (int4 loads), 4 independent atomic+store chains.
// ---------------------------------------------------------------------------
__global__ void scatter_kernel(const int* __restrict__ ei) {
    int v = blockIdx.x * blockDim.x + threadIdx.x;
    if (v >= E / 4) return;
    int4 s4 = __ldg(reinterpret_cast<const int4*>(ei) + v);
    int4 d4 = __ldg(reinterpret_cast<const int4*>(ei + E) + v);
    int e0 = v * 4;
    int p0 = atomicAdd(&g_cur[d4.x], 1);
    int p1 = atomicAdd(&g_cur[d4.y], 1);
    int p2 = atomicAdd(&g_cur[d4.z], 1);
    int p3 = atomicAdd(&g_cur[d4.w], 1);
    g_perm[p0] = make_uint2((unsigned)(e0),     (unsigned)s4.x);
    g_perm[p1] = make_uint2((unsigned)(e0 + 1), (unsigned)s4.y);
    g_perm[p2] = make_uint2((unsigned)(e0 + 2), (unsigned)s4.z);
    g_perm[p3] = make_uint2((unsigned)(e0 + 3), (unsigned)s4.w);
}

// ---------------------------------------------------------------------------
// Aggregate: one warp per node. acc = x[i] + sum relu(x[src] + ea[e]).
// ea via __ldcs (streaming, keeps x L2-resident). Inner loop de-predicated:
// unconditional 4-edge groups for m&~3 edges + scalar remainder, so the
// common partial batch (avg degree 16) issues clean 8-load bursts.
// ---------------------------------------------------------------------------
__global__ __launch_bounds__(256)
void aggregate_kernel(const float* __restrict__ x, const float* __restrict__ ea) {
    int node = (int)(((size_t)blockIdx.x * blockDim.x + threadIdx.x) >> 5);
    int lane = threadIdx.x & 31;
    if (node >= Nn) return;
    const float4* x4  = reinterpret_cast<const float4*>(x);
    const float4* ea4 = reinterpret_cast<const float4*>(ea);
    float4 acc = __ldg(x4 + (size_t)node * 32 + lane);   // seed with x_i
    int start = g_start[node];
    int cnt   = g_cnt[node];
    for (int base = 0; base < cnt; base += 32) {
        int m = cnt - base; if (m > 32) m = 32;
        uint2 p = make_uint2(0u, 0u);
        if (lane < m) p = __ldg(g_perm + start + base + lane);
        int m4 = m & ~3;
        for (int j = 0; j < m4; j += 4) {
            uint32_t e0 = __shfl_sync(0xffffffffu, p.x, j);
            uint32_t s0 = __shfl_sync(0xffffffffu, p.y, j);
            uint32_t e1 = __shfl_sync(0xffffffffu, p.x, j + 1);
            uint32_t s1 = __shfl_sync(0xffffffffu, p.y, j + 1);
            uint32_t e2 = __shfl_sync(0xffffffffu, p.x, j + 2);
            uint32_t s2 = __shfl_sync(0xffffffffu, p.y, j + 2);
            uint32_t e3 = __shfl_sync(0xffffffffu, p.x, j + 3);
            uint32_t s3 = __shfl_sync(0xffffffffu, p.y, j + 3);
            float4 xa = __ldg(x4 + (size_t)s0 * 32 + lane);
            float4 va = __ldcs(ea4 + (size_t)e0 * 32 + lane);
            float4 xb = __ldg(x4 + (size_t)s1 * 32 + lane);
            float4 vb = __ldcs(ea4 + (size_t)e1 * 32 + lane);
            float4 xc = __ldg(x4 + (size_t)s2 * 32 + lane);
            float4 vc = __ldcs(ea4 + (size_t)e2 * 32 + lane);
            float4 xd = __ldg(x4 + (size_t)s3 * 32 + lane);
            float4 vd = __ldcs(ea4 + (size_t)e3 * 32 + lane);
            acc.x += fmaxf(xa.x + va.x, 0.f); acc.y += fmaxf(xa.y + va.y, 0.f);
            acc.z += fmaxf(xa.z + va.z, 0.f); acc.w += fmaxf(xa.w + va.w, 0.f);
            acc.x += fmaxf(xb.x + vb.x, 0.f); acc.y += fmaxf(xb.y + vb.y, 0.f);
            acc.z += fmaxf(xb.z + vb.z, 0.f); acc.w += fmaxf(xb.w + vb.w, 0.f);
            acc.x += fmaxf(xc.x + vc.x, 0.f); acc.y += fmaxf(xc.y + vc.y, 0.f);
            acc.z += fmaxf(xc.z + vc.z, 0.f); acc.w += fmaxf(xc.w + vc.w, 0.f);
            acc.x += fmaxf(xd.x + vd.x, 0.f); acc.y += fmaxf(xd.y + vd.y, 0.f);
            acc.z += fmaxf(xd.z + vd.z, 0.f); acc.w += fmaxf(xd.w + vd.w, 0.f);
        }
        for (int j = m4; j < m; j++) {
            uint32_t e = __shfl_sync(0xffffffffu, p.x, j);
            uint32_t s = __shfl_sync(0xffffffffu, p.y, j);
            float4 xv = __ldg(x4 + (size_t)s * 32 + lane);
            float4 ev = __ldcs(ea4 + (size_t)e * 32 + lane);
            acc.x += fmaxf(xv.x + ev.x, 0.f);
            acc.y += fmaxf(xv.y + ev.y, 0.f);
            acc.z += fmaxf(xv.z + ev.z, 0.f);
            acc.w += fmaxf(xv.w + ev.w, 0.f);
        }
    }
    *(reinterpret_cast<float4*>(g_aggr) + (size_t)node * 32 + lane) = acc;
}

// ---------------------------------------------------------------------------
// Tensor-core MLP, 64x128x128 tile per block, 256 threads (8 warps, 2x4 grid),
// 97 KB smem -> 2 blocks/SM. Identical to 206.9us version.
//   mode 0: A = g_aggr (= x+aggr); g_t = relu(A@W1 + b1)
//   mode 1: A = g_t;               out = x + A@W2 + b2  (+ BN column stats)
// ---------------------------------------------------------------------------
#define MMA_BF16(d, av, b0, b1) \
    asm volatile("mma.sync.aligned.m16n8k16.row.col.f32.bf16.bf16.f32 " \
                 "{%0,%1,%2,%3},{%4,%5,%6,%7},{%8,%9},{%0,%1,%2,%3};" \
                 : "+f"((d)[0]), "+f"((d)[1]), "+f"((d)[2]), "+f"((d)[3]) \
                 : "r"((av).x), "r"((av).y), "r"((av).z), "r"((av).w), \
                   "r"(b0), "r"(b1))

__global__ __launch_bounds__(256, 2)
void mlp_tc(const float* __restrict__ x, const float* __restrict__ bias,
            float* __restrict__ out, int mode) {
    extern __shared__ __align__(16) unsigned char smem[];
    uint32_t* Ah = reinterpret_cast<uint32_t*>(smem);   // [4096]
    uint32_t* Al = Ah + 4096;                           // [4096]
    uint32_t* Bh = Al + 4096;                           // [8192]
    uint32_t* Bl = Bh + 8192;                           // [8192]
    float* cs = reinterpret_cast<float*>(Bl + 8192);    // [128]
    float* cq = cs + 128;
    const int tid = threadIdx.x, wid = tid >> 5, lane = tid & 31;
    const int r0 = blockIdx.x * 64;

    {
        const uint4* sh = reinterpret_cast<const uint4*>(g_Bh[mode]);
        const uint4* sl = reinterpret_cast<const uint4*>(g_Bl[mode]);
        uint4* dh = reinterpret_cast<uint4*>(Bh);
        uint4* dl = reinterpret_cast<uint4*>(Bl);
#pragma unroll
        for (int i = tid; i < 2048; i += 256) { dh[i] = __ldg(sh + i); dl[i] = __ldg(sl + i); }
    }

#pragma unroll
    for (int i = tid; i < 2048; i += 256) {
        int r = i >> 5, q = i & 31;
        int gr = r0 + r;
        float4 a = make_float4(0.f, 0.f, 0.f, 0.f);
        if (gr < Nn) {
            const float* src = mode == 0 ? g_aggr : g_t;
            a = *(reinterpret_cast<const float4*>(src) + (size_t)gr * 32 + q);
        }
        __nv_bfloat16 h0 = __float2bfloat16(a.x), h1 = __float2bfloat16(a.y);
        __nv_bfloat16 h2 = __float2bfloat16(a.z), h3 = __float2bfloat16(a.w);
        __nv_bfloat16 l0 = __float2bfloat16(a.x - __bfloat162float(h0));
        __nv_bfloat16 l1 = __float2bfloat16(a.y - __bfloat162float(h1));
        __nv_bfloat16 l2 = __float2bfloat16(a.z - __bfloat162float(h2));
        __nv_bfloat16 l3 = __float2bfloat16(a.w - __bfloat162float(h3));
        uint32_t hp0 = (uint32_t)__bfloat16_as_ushort(h0) | ((uint32_t)__bfloat16_as_ushort(h1) << 16);
        uint32_t hp1 = (uint32_t)__bfloat16_as_ushort(h2) | ((uint32_t)__bfloat16_as_ushort(h3) << 16);
        uint32_t lp0 = (uint32_t)__bfloat16_as_ushort(l0) | ((uint32_t)__bfloat16_as_ushort(l1) << 16);
        uint32_t lp1 = (uint32_t)__bfloat16_as_ushort(l2) | ((uint32_t)__bfloat16_as_ushort(l3) << 16);
        int kstep = q >> 2;
        int m16   = r >> 4;
        int l     = (r & 7) * 4 + (q & 1) * 2;
        int s     = ((r >> 3) & 1) + 2 * ((q >> 1) & 1);
        int base  = (kstep * 4 + m16) * 32;
        int i0 = (base + ((l)     ^ kstep)) * 4 + s;
        int i1 = (base + ((l + 1) ^ kstep)) * 4 + s;
        Ah[i0] = hp0; Ah[i1] = hp1;
        Al[i0] = lp0; Al[i1] = lp1;
    }
    if (tid < 128) { cs[tid] = 0.f; cq[tid] = 0.f; }
    __syncthreads();

    const int wm = wid & 1, wn = wid >> 1;   // 2x4 warp grid, 32x32 per warp
    float acc[2][2][2][4];
#pragma unroll
    for (int im = 0; im < 2; im++)
#pragma unroll
        for (int in = 0; in < 2; in++)
#pragma unroll
            for (int j = 0; j < 2; j++)
#pragma unroll
                for (int v = 0; v < 4; v++) acc[im][in][j][v] = 0.f;

#pragma unroll
    for (int ks = 0; ks < 8; ks++) {
        uint4 ahv[2], alv[2], bhv[2], blv[2];
#pragma unroll
        for (int im = 0; im < 2; im++) {
            int idx = ((ks * 4 + wm * 2 + im) * 32 + (lane ^ ks)) * 4;
            ahv[im] = *reinterpret_cast<const uint4*>(Ah + idx);
            alv[im] = *reinterpret_cast<const uint4*>(Al + idx);
        }
#pragma unroll
        for (int in = 0; in < 2; in++) {
            int idx = ((ks * 8 + wn * 2 + in) * 32 + lane) * 4;
            bhv[in] = *reinterpret_cast<const uint4*>(Bh + idx);
            blv[in] = *reinterpret_cast<const uint4*>(Bl + idx);
        }
#pragma unroll
        for (int im = 0; im < 2; im++)
#pragma unroll
            for (int in = 0; in < 2; in++)
#pragma unroll
                for (int j = 0; j < 2; j++) {
                    uint32_t b0h = j ? bhv[in].z : bhv[in].x;
                    uint32_t b1h = j ? bhv[in].w : bhv[in].y;
                    uint32_t b0l = j ? blv[in].z : blv[in].x;
                    uint32_t b1l = j ? blv[in].w : blv[in].y;
                    MMA_BF16(acc[im][in][j], ahv[im], b0h, b1h);
                    MMA_BF16(acc[im][in][j], ahv[im], b0l, b1l);
                    MMA_BF16(acc[im][in][j], alv[im], b0h, b1h);
                }
    }

    const int tg = lane >> 2, tc = lane & 3;
    float2 bv[2][2];
#pragma unroll
    for (int in = 0; in < 2; in++)
#pragma unroll
        for (int j = 0; j < 2; j++)
            bv[in][j] = __ldg(reinterpret_cast<const float2*>(bias + wn * 32 + in * 16 + j * 8 + tc * 2));

    if (mode == 0) {
#pragma unroll
        for (int im = 0; im < 2; im++)
#pragma unroll
            for (int rh = 0; rh < 2; rh++) {
                int gr = r0 + (wm * 2 + im) * 16 + rh * 8 + tg;
                if (gr < Nn) {
                    float* op = g_t + (size_t)gr * D;
#pragma unroll
                    for (int in = 0; in < 2; in++)
#pragma unroll
                        for (int j = 0; j < 2; j++) {
                            int col = wn * 32 + in * 16 + j * 8 + tc * 2;
                            float2 v;
                            v.x = fmaxf(acc[im][in][j][rh * 2]     + bv[in][j].x, 0.f);
                            v.y = fmaxf(acc[im][in][j][rh * 2 + 1] + bv[in][j].y, 0.f);
                            *reinterpret_cast<float2*>(op + col) = v;
                        }
                }
            }
    } else {
        float s8[8], q8[8];
#pragma unroll
        for (int u = 0; u < 8; u++) { s8[u] = 0.f; q8[u] = 0.f; }
#pragma unroll
        for (int im = 0; im < 2; im++)
#pragma unroll
            for (int rh = 0; rh < 2; rh++) {
                int gr = r0 + (wm * 2 + im) * 16 + rh * 8 + tg;
                if (gr < Nn) {
                    const float* xr = x + (size_t)gr * D;
                    float* op = out + (size_t)gr * D;
#pragma unroll
                    for (int in = 0; in < 2; in++)
#pragma unroll
                        for (int j = 0; j < 2; j++) {
                            int col = wn * 32 + in * 16 + j * 8 + tc * 2;
                            float2 xv = __ldg(reinterpret_cast<const float2*>(xr + col));
                            float v0 = acc[im][in][j][rh * 2]     + bv[in][j].x + xv.x;
                            float v1 = acc[im][in][j][rh * 2 + 1] + bv[in][j].y + xv.y;
                            int ci = in * 4 + j * 2;
                            s8[ci] += v0;     q8[ci] += v0 * v0;
                            s8[ci + 1] += v1; q8[ci + 1] += v1 * v1;
                            *reinterpret_cast<float2*>(op + col) = make_float2(v0, v1);
                        }
                }
            }
#pragma unroll
        for (int in = 0; in < 2; in++)
#pragma unroll
            for (int j = 0; j < 2; j++)
#pragma unroll
                for (int h = 0; h < 2; h++) {
                    int col = wn * 32 + in * 16 + j * 8 + tc * 2 + h;
                    int ci = in * 4 + j * 2 + h;
                    atomicAdd(&cs[col], s8[ci]);
                    atomicAdd(&cq[col], q8[ci]);
                }
        __syncthreads();
        if (tid < 128) {
            atomicAdd(&g_stats[tid],     cs[tid]);
            atomicAdd(&g_stats[D + tid], cq[tid]);
        }
    }
}

// ---------------------------------------------------------------------------
// BN: per-block recompute of scale/shift from stats, then in-place apply.
// ---------------------------------------------------------------------------
__global__ void bn_kernel(float* __restrict__ out,
                          const float* __restrict__ bn_w,
                          const float* __restrict__ bn_b) {
    __shared__ float sc_s[D], sh_s[D];
    int tid = threadIdx.x;
    if (tid < D) {
        float inv_n = 1.f / (float)Nn;
        float mean  = g_stats[tid] * inv_n;
        float var   = g_stats[D + tid] * inv_n - mean * mean;
        float rstd  = rsqrtf(var + 1e-5f);
        float sc    = rstd * __ldg(bn_w + tid);
        sc_s[tid] = sc;
        sh_s[tid] = __ldg(bn_b + tid) - mean * sc;
    }
    __syncthreads();
    size_t stride = (size_t)gridDim.x * blockDim.x;
    size_t total  = (size_t)Nn * 32;
    for (size_t v = (size_t)blockIdx.x * blockDim.x + tid; v < total; v += stride) {
        int q = (int)(v & 31);
        float4 h = reinterpret_cast<float4*>(out)[v];
        float4 sc = *reinterpret_cast<const float4*>(sc_s + q * 4);
        float4 sh = *reinterpret_cast<const float4*>(sh_s + q * 4);
        h.x = h.x * sc.x + sh.x;
        h.y = h.y * sc.y + sh.y;
        h.z = h.z * sc.z + sh.z;
        h.w = h.w * sc.w + sh.w;
        reinterpret_cast<float4*>(out)[v] = h;
    }
}

// ---------------------------------------------------------------------------
extern "C" void kernel_launch(void* const* d_in, const int* in_sizes, int n_in,
                              void* d_out, int out_size) {
    const float* x   = (const float*)d_in[0];
    const int*   ei  = (const int*)d_in[1];
    const float* ea  = (const float*)d_in[2];
    const float* W1  = (const float*)d_in[3];
    const float* b1  = (const float*)d_in[4];
    const float* W2  = (const float*)d_in[5];
    const float* b2  = (const float*)d_in[6];
    const float* bnw = (const float*)d_in[7];
    const float* bnb = (const float*)d_in[8];
    float* out = (float*)d_out;

    init_kernel<<<2 + (Nn + 255) / 256, 256>>>(W1, W2);      // (1)
    hist_kernel<<<(E / 4 + 255) / 256, 256>>>(ei);           // (2)
    scan_kernel<<<SCAN_G, SCAN_B>>>();                       // (3)
    scatter_kernel<<<(E / 4 + 255) / 256, 256>>>(ei);        // (4) <- ncu window
    aggregate_kernel<<<(Nn * 32 + 255) / 256, 256>>>(x, ea); // (5)

    int smem_bytes = (4096 * 2 + 8192 * 2 + 256) * 4;        // 99,328 B
    cudaFuncSetAttribute(mlp_tc, cudaFuncAttributeMaxDynamicSharedMemorySize, smem_bytes);
    int grid = (Nn + 63) / 64;
    mlp_tc<<<grid, 256, smem_bytes>>>(x, b1, nullptr, 0);    // (6)
    mlp_tc<<<grid, 256, smem_bytes>>>(x, b2, out, 1);        // (7)

    bn_kernel<<<2048, 256>>>(out, bnw, bnb);                 // (8)
}

// round 15
// speedup vs baseline: 1.0456x; 1.0285x over previous
#include <cuda_runtime.h>
#include <cuda_bf16.h>
#include <cstdint>

// Problem constants
constexpr int Nn = 50000;
constexpr int D  = 128;
constexpr int E  = 800000;
constexpr int SCAN_B = 512;
constexpr int SCAN_G = (Nn + SCAN_B - 1) / SCAN_B;   // 98

// Scratch (static device globals; zero-initialized at module load, and each
// graph replay restores the zeroed state it needs before exiting).
__device__ float g_aggr[(size_t)Nn * D];   // holds h = x + aggr
__device__ float g_t[(size_t)Nn * D];
__device__ float g_stats[2 * D];
__device__ int   g_cnt[Nn];
__device__ int   g_start[Nn];
__device__ int   g_cur[Nn];
__device__ int   g_desc[SCAN_G];           // decoupled-lookback descriptors
__device__ uint2 g_perm[E];                // (edge_id, src), sorted by dst
// W1/W2 split bf16 hi/lo, fragment-major for m16n8k16 B-operand
__device__ uint32_t g_Bh[2][8192];
__device__ uint32_t g_Bl[2][8192];

// ---------------------------------------------------------------------------
// hist: blocks 0-1 pack W1/W2 (bf16 hi/lo fragment-major); blocks 2+ do the
// dst histogram (4 edges/thread, int4). g_cnt is zero on entry (module-load
// zero-init on first call; bn_kernel cleanup on every subsequent replay).
// ---------------------------------------------------------------------------
__global__ void hist_kernel(const int* __restrict__ ei,
                            const float* __restrict__ W1,
                            const float* __restrict__ W2) {
    if (blockIdx.x < 2) {
        const float* W = blockIdx.x ? W2 : W1;
        uint32_t* bh = g_Bh[blockIdx.x];
        uint32_t* bl = g_Bl[blockIdx.x];
        for (int i = threadIdx.x; i < 64 * 128; i += blockDim.x) {
            int k2 = i >> 7, c = i & 127, k = k2 * 2;
            float w0 = __ldg(W + (size_t)k * D + c);
            float w1 = __ldg(W + (size_t)(k + 1) * D + c);
            __nv_bfloat16 h0 = __float2bfloat16(w0);
            __nv_bfloat16 h1 = __float2bfloat16(w1);
            __nv_bfloat16 l0 = __float2bfloat16(w0 - __bfloat162float(h0));
            __nv_bfloat16 l1 = __float2bfloat16(w1 - __bfloat162float(h1));
            int kstep = k2 >> 3;
            int n16   = c >> 4;
            int lane  = (c & 7) * 4 + (k2 & 3);
            int slot  = 2 * ((c >> 3) & 1) + ((k2 >> 2) & 1);
            int idx   = ((kstep * 8 + n16) * 32 + lane) * 4 + slot;
            bh[idx] = (uint32_t)__bfloat16_as_ushort(h0) | ((uint32_t)__bfloat16_as_ushort(h1) << 16);
            bl[idx] = (uint32_t)__bfloat16_as_ushort(l0) | ((uint32_t)__bfloat16_as_ushort(l1) << 16);
        }
    } else {
        int v = (blockIdx.x - 2) * blockDim.x + threadIdx.x;
        if (v < E / 4) {
            int4 d4 = __ldg(reinterpret_cast<const int4*>(ei + E) + v);
            atomicAdd(&g_cnt[d4.x], 1);
            atomicAdd(&g_cnt[d4.y], 1);
            atomicAdd(&g_cnt[d4.z], 1);
            atomicAdd(&g_cnt[d4.w], 1);
        }
    }
}

// ---------------------------------------------------------------------------
// Single-kernel exclusive scan over g_cnt via decoupled lookback.
// g_desc is zero on entry (module-load zero-init / scatter cleanup).
// ---------------------------------------------------------------------------
__global__ __launch_bounds__(SCAN_B)
void scan_kernel() {
    __shared__ int sm[SCAN_B];
    __shared__ int s_prefix;
    const int b = blockIdx.x;
    const int t = threadIdx.x;
    int i = b * SCAN_B + t;
    int v = (i < Nn) ? g_cnt[i] : 0;
    sm[t] = v;
    __syncthreads();
#pragma unroll
    for (int off = 1; off < SCAN_B; off <<= 1) {
        int tmp = (t >= off) ? sm[t - off] : 0;
        __syncthreads();
        sm[t] += tmp;
        __syncthreads();
    }
    int total = sm[SCAN_B - 1];

    if (b == 0) {
        if (t == 0) {
            atomicExch(&g_desc[0], (total << 2) | 2);
            s_prefix = 0;
        }
    } else {
        if (t == 0) atomicExch(&g_desc[b], (total << 2) | 1);
        if (t < 32) {
            int prefix = 0, offset = 0;
            bool done = false;
            while (!done) {
                int j = b - 1 - offset - t;
                int d;
                if (j >= 0) {
                    do { d = atomicAdd(&g_desc[j], 0); } while ((d & 3) == 0);
                } else {
                    d = 2;
                }
                unsigned mask = __ballot_sync(0xffffffffu, (d & 3) == 2);
                int contrib;
                if (mask) {
                    int firstP = __ffs(mask) - 1;
                    contrib = (t <= firstP) ? (d >> 2) : 0;
                    done = true;
                } else {
                    contrib = d >> 2;
                }
#pragma unroll
                for (int o = 16; o; o >>= 1) contrib += __shfl_xor_sync(0xffffffffu, contrib, o);
                prefix += contrib;
                offset += 32;
            }
            if (t == 0) {
                atomicExch(&g_desc[b], ((prefix + total) << 2) | 2);
                s_prefix = prefix;
            }
        }
    }
    __syncthreads();
    int s = sm[t] - v + s_prefix;
    if (i < Nn) { g_start[i] = s; g_cur[i] = s; }
}

// ---------------------------------------------------------------------------
// Scatter: 1 edge/thread (R12-proven config; contention-bound, batching does
// not help). Block 0 additionally zeroes g_stats + g_desc for this replay
// (safe: scan already consumed g_desc; mlp mode1 accumulates g_stats later).
// ---------------------------------------------------------------------------
__global__ void scatter_kernel(const int* __restrict__ ei) {
    if (blockIdx.x == 0) {
        if (threadIdx.x < 2 * D) g_stats[threadIdx.x] = 0.f;
        if (threadIdx.x < SCAN_G) g_desc[threadIdx.x] = 0;
    }
    int e = blockIdx.x * blockDim.x + threadIdx.x;
    if (e < E) {
        int src = __ldg(ei + e);
        int dst = __ldg(ei + E + e);
        int pos = atomicAdd(&g_cur[dst], 1);
        g_perm[pos] = make_uint2((unsigned)e, (unsigned)src);
    }
}

// ---------------------------------------------------------------------------
// Aggregate: one warp per node. acc = x[i] + sum relu(x[src] + ea[e]).
// ea via __ldcs (streaming, keeps x L2-resident). De-predicated inner loop.
// ---------------------------------------------------------------------------
__global__ __launch_bounds__(256)
void aggregate_kernel(const float* __restrict__ x, const float* __restrict__ ea) {
    int node = (int)(((size_t)blockIdx.x * blockDim.x + threadIdx.x) >> 5);
    int lane = threadIdx.x & 31;
    if (node >= Nn) return;
    const float4* x4  = reinterpret_cast<const float4*>(x);
    const float4* ea4 = reinterpret_cast<const float4*>(ea);
    float4 acc = __ldg(x4 + (size_t)node * 32 + lane);   // seed with x_i
    int start = g_start[node];
    int cnt   = g_cnt[node];
    for (int base = 0; base < cnt; base += 32) {
        int m = cnt - base; if (m > 32) m = 32;
        uint2 p = make_uint2(0u, 0u);
        if (lane < m) p = __ldg(g_perm + start + base + lane);
        int m4 = m & ~3;
        for (int j = 0; j < m4; j += 4) {
            uint32_t e0 = __shfl_sync(0xffffffffu, p.x, j);
            uint32_t s0 = __shfl_sync(0xffffffffu, p.y, j);
            uint32_t e1 = __shfl_sync(0xffffffffu, p.x, j + 1);
            uint32_t s1 = __shfl_sync(0xffffffffu, p.y, j + 1);
            uint32_t e2 = __shfl_sync(0xffffffffu, p.x, j + 2);
            uint32_t s2 = __shfl_sync(0xffffffffu, p.y, j + 2);
            uint32_t e3 = __shfl_sync(0xffffffffu, p.x, j + 3);
            uint32_t s3 = __shfl_sync(0xffffffffu, p.y, j + 3);
            float4 xa = __ldg(x4 + (size_t)s0 * 32 + lane);
            float4 va = __ldcs(ea4 + (size_t)e0 * 32 + lane);
            float4 xb = __ldg(x4 + (size_t)s1 * 32 + lane);
            float4 vb = __ldcs(ea4 + (size_t)e1 * 32 + lane);
            float4 xc = __ldg(x4 + (size_t)s2 * 32 + lane);
            float4 vc = __ldcs(ea4 + (size_t)e2 * 32 + lane);
            float4 xd = __ldg(x4 + (size_t)s3 * 32 + lane);
            float4 vd = __ldcs(ea4 + (size_t)e3 * 32 + lane);
            acc.x += fmaxf(xa.x + va.x, 0.f); acc.y += fmaxf(xa.y + va.y, 0.f);
            acc.z += fmaxf(xa.z + va.z, 0.f); acc.w += fmaxf(xa.w + va.w, 0.f);
            acc.x += fmaxf(xb.x + vb.x, 0.f); acc.y += fmaxf(xb.y + vb.y, 0.f);
            acc.z += fmaxf(xb.z + vb.z, 0.f); acc.w += fmaxf(xb.w + vb.w, 0.f);
            acc.x += fmaxf(xc.x + vc.x, 0.f); acc.y += fmaxf(xc.y + vc.y, 0.f);
            acc.z += fmaxf(xc.z + vc.z, 0.f); acc.w += fmaxf(xc.w + vc.w, 0.f);
            acc.x += fmaxf(xd.x + vd.x, 0.f); acc.y += fmaxf(xd.y + vd.y, 0.f);
            acc.z += fmaxf(xd.z + vd.z, 0.f); acc.w += fmaxf(xd.w + vd.w, 0.f);
        }
        for (int j = m4; j < m; j++) {
            uint32_t e = __shfl_sync(0xffffffffu, p.x, j);
            uint32_t s = __shfl_sync(0xffffffffu, p.y, j);
            float4 xv = __ldg(x4 + (size_t)s * 32 + lane);
            float4 ev = __ldcs(ea4 + (size_t)e * 32 + lane);
            acc.x += fmaxf(xv.x + ev.x, 0.f);
            acc.y += fmaxf(xv.y + ev.y, 0.f);
            acc.z += fmaxf(xv.z + ev.z, 0.f);
            acc.w += fmaxf(xv.w + ev.w, 0.f);
        }
    }
    *(reinterpret_cast<float4*>(g_aggr) + (size_t)node * 32 + lane) = acc;
}

// ---------------------------------------------------------------------------
// Tensor-core MLP, 64x128x128 tile per block, 256 threads (8 warps, 2x4 grid),
// 97 KB smem -> 2 blocks/SM. Unchanged from 205.5us version.
//   mode 0: A = g_aggr (= x+aggr); g_t = relu(A@W1 + b1)
//   mode 1: A = g_t;               out = x + A@W2 + b2  (+ BN column stats)
// ---------------------------------------------------------------------------
#define MMA_BF16(d, av, b0, b1) \
    asm volatile("mma.sync.aligned.m16n8k16.row.col.f32.bf16.bf16.f32 " \
                 "{%0,%1,%2,%3},{%4,%5,%6,%7},{%8,%9},{%0,%1,%2,%3};" \
                 : "+f"((d)[0]), "+f"((d)[1]), "+f"((d)[2]), "+f"((d)[3]) \
                 : "r"((av).x), "r"((av).y), "r"((av).z), "r"((av).w), \
                   "r"(b0), "r"(b1))

__global__ __launch_bounds__(256, 2)
void mlp_tc(const float* __restrict__ x, const float* __restrict__ bias,
            float* __restrict__ out, int mode) {
    extern __shared__ __align__(16) unsigned char smem[];
    uint32_t* Ah = reinterpret_cast<uint32_t*>(smem);   // [4096]
    uint32_t* Al = Ah + 4096;                           // [4096]
    uint32_t* Bh = Al + 4096;                           // [8192]
    uint32_t* Bl = Bh + 8192;                           // [8192]
    float* cs = reinterpret_cast<float*>(Bl + 8192);    // [128]
    float* cq = cs + 128;
    const int tid = threadIdx.x, wid = tid >> 5, lane = tid & 31;
    const int r0 = blockIdx.x * 64;

    {
        const uint4* sh = reinterpret_cast<const uint4*>(g_Bh[mode]);
        const uint4* sl = reinterpret_cast<const uint4*>(g_Bl[mode]);
        uint4* dh = reinterpret_cast<uint4*>(Bh);
        uint4* dl = reinterpret_cast<uint4*>(Bl);
#pragma unroll
        for (int i = tid; i < 2048; i += 256) { dh[i] = __ldg(sh + i); dl[i] = __ldg(sl + i); }
    }

#pragma unroll
    for (int i = tid; i < 2048; i += 256) {
        int r = i >> 5, q = i & 31;
        int gr = r0 + r;
        float4 a = make_float4(0.f, 0.f, 0.f, 0.f);
        if (gr < Nn) {
            const float* src = mode == 0 ? g_aggr : g_t;
            a = *(reinterpret_cast<const float4*>(src) + (size_t)gr * 32 + q);
        }
        __nv_bfloat16 h0 = __float2bfloat16(a.x), h1 = __float2bfloat16(a.y);
        __nv_bfloat16 h2 = __float2bfloat16(a.z), h3 = __float2bfloat16(a.w);
        __nv_bfloat16 l0 = __float2bfloat16(a.x - __bfloat162float(h0));
        __nv_bfloat16 l1 = __float2bfloat16(a.y - __bfloat162float(h1));
        __nv_bfloat16 l2 = __float2bfloat16(a.z - __bfloat162float(h2));
        __nv_bfloat16 l3 = __float2bfloat16(a.w - __bfloat162float(h3));
        uint32_t hp0 = (uint32_t)__bfloat16_as_ushort(h0) | ((uint32_t)__bfloat16_as_ushort(h1) << 16);
        uint32_t hp1 = (uint32_t)__bfloat16_as_ushort(h2) | ((uint32_t)__bfloat16_as_ushort(h3) << 16);
        uint32_t lp0 = (uint32_t)__bfloat16_as_ushort(l0) | ((uint32_t)__bfloat16_as_ushort(l1) << 16);
        uint32_t lp1 = (uint32_t)__bfloat16_as_ushort(l2) | ((uint32_t)__bfloat16_as_ushort(l3) << 16);
        int kstep = q >> 2;
        int m16   = r >> 4;
        int l     = (r & 7) * 4 + (q & 1) * 2;
        int s     = ((r >> 3) & 1) + 2 * ((q >> 1) & 1);
        int base  = (kstep * 4 + m16) * 32;
        int i0 = (base + ((l)     ^ kstep)) * 4 + s;
        int i1 = (base + ((l + 1) ^ kstep)) * 4 + s;
        Ah[i0] = hp0; Ah[i1] = hp1;
        Al[i0] = lp0; Al[i1] = lp1;
    }
    if (tid < 128) { cs[tid] = 0.f; cq[tid] = 0.f; }
    __syncthreads();

    const int wm = wid & 1, wn = wid >> 1;   // 2x4 warp grid, 32x32 per warp
    float acc[2][2][2][4];
#pragma unroll
    for (int im = 0; im < 2; im++)
#pragma unroll
        for (int in = 0; in < 2; in++)
#pragma unroll
            for (int j = 0; j < 2; j++)
#pragma unroll
                for (int v = 0; v < 4; v++) acc[im][in][j][v] = 0.f;

#pragma unroll
    for (int ks = 0; ks < 8; ks++) {
        uint4 ahv[2], alv[2], bhv[2], blv[2];
#pragma unroll
        for (int im = 0; im < 2; im++) {
            int idx = ((ks * 4 + wm * 2 + im) * 32 + (lane ^ ks)) * 4;
            ahv[im] = *reinterpret_cast<const uint4*>(Ah + idx);
            alv[im] = *reinterpret_cast<const uint4*>(Al + idx);
        }
#pragma unroll
        for (int in = 0; in < 2; in++) {
            int idx = ((ks * 8 + wn * 2 + in) * 32 + lane) * 4;
            bhv[in] = *reinterpret_cast<const uint4*>(Bh + idx);
            blv[in] = *reinterpret_cast<const uint4*>(Bl + idx);
        }
#pragma unroll
        for (int im = 0; im < 2; im++)
#pragma unroll
            for (int in = 0; in < 2; in++)
#pragma unroll
                for (int j = 0; j < 2; j++) {
                    uint32_t b0h = j ? bhv[in].z : bhv[in].x;
                    uint32_t b1h = j ? bhv[in].w : bhv[in].y;
                    uint32_t b0l = j ? blv[in].z : blv[in].x;
                    uint32_t b1l = j ? blv[in].w : blv[in].y;
                    MMA_BF16(acc[im][in][j], ahv[im], b0h, b1h);
                    MMA_BF16(acc[im][in][j], ahv[im], b0l, b1l);
                    MMA_BF16(acc[im][in][j], alv[im], b0h, b1h);
                }
    }

    const int tg = lane >> 2, tc = lane & 3;
    float2 bv[2][2];
#pragma unroll
    for (int in = 0; in < 2; in++)
#pragma unroll
        for (int j = 0; j < 2; j++)
            bv[in][j] = __ldg(reinterpret_cast<const float2*>(bias + wn * 32 + in * 16 + j * 8 + tc * 2));

    if (mode == 0) {
#pragma unroll
        for (int im = 0; im < 2; im++)
#pragma unroll
            for (int rh = 0; rh < 2; rh++) {
                int gr = r0 + (wm * 2 + im) * 16 + rh * 8 + tg;
                if (gr < Nn) {
                    float* op = g_t + (size_t)gr * D;
#pragma unroll
                    for (int in = 0; in < 2; in++)
#pragma unroll
                        for (int j = 0; j < 2; j++) {
                            int col = wn * 32 + in * 16 + j * 8 + tc * 2;
                            float2 v;
                            v.x = fmaxf(acc[im][in][j][rh * 2]     + bv[in][j].x, 0.f);
                            v.y = fmaxf(acc[im][in][j][rh * 2 + 1] + bv[in][j].y, 0.f);
                            *reinterpret_cast<float2*>(op + col) = v;
                        }
                }
            }
    } else {
        float s8[8], q8[8];
#pragma unroll
        for (int u = 0; u < 8; u++) { s8[u] = 0.f; q8[u] = 0.f; }
#pragma unroll
        for (int im = 0; im < 2; im++)
#pragma unroll
            for (int rh = 0; rh < 2; rh++) {
                int gr = r0 + (wm * 2 + im) * 16 + rh * 8 + tg;
                if (gr < Nn) {
                    const float* xr = x + (size_t)gr * D;
                    float* op = out + (size_t)gr * D;
#pragma unroll
                    for (int in = 0; in < 2; in++)
#pragma unroll
                        for (int j = 0; j < 2; j++) {
                            int col = wn * 32 + in * 16 + j * 8 + tc * 2;
                            float2 xv = __ldg(reinterpret_cast<const float2*>(xr + col));
                            float v0 = acc[im][in][j][rh * 2]     + bv[in][j].x + xv.x;
                            float v1 = acc[im][in][j][rh * 2 + 1] + bv[in][j].y + xv.y;
                            int ci = in * 4 + j * 2;
                            s8[ci] += v0;     q8[ci] += v0 * v0;
                            s8[ci + 1] += v1; q8[ci + 1] += v1 * v1;
                            *reinterpret_cast<float2*>(op + col) = make_float2(v0, v1);
                        }
                }
            }
#pragma unroll
        for (int in = 0; in < 2; in++)
#pragma unroll
            for (int j = 0; j < 2; j++)
#pragma unroll
                for (int h = 0; h < 2; h++) {
                    int col = wn * 32 + in * 16 + j * 8 + tc * 2 + h;
                    int ci = in * 4 + j * 2 + h;
                    atomicAdd(&cs[col], s8[ci]);
                    atomicAdd(&cq[col], q8[ci]);
                }
        __syncthreads();
        if (tid < 128) {
            atomicAdd(&g_stats[tid],     cs[tid]);
            atomicAdd(&g_stats[D + tid], cq[tid]);
        }
    }
}

// ---------------------------------------------------------------------------
// BN: per-block recompute of scale/shift from stats, in-place apply, then
// zero g_cnt for the next graph replay (bn never reads g_cnt -> race-free).
// ---------------------------------------------------------------------------
__global__ void bn_kernel(float* __restrict__ out,
                          const float* __restrict__ bn_w,
                          const float* __restrict__ bn_b) {
    __shared__ float sc_s[D], sh_s[D];
    int tid = threadIdx.x;
    if (tid < D) {
        float inv_n = 1.f / (float)Nn;
        float mean  = g_stats[tid] * inv_n;
        float var   = g_stats[D + tid] * inv_n - mean * mean;
        float rstd  = rsqrtf(var + 1e-5f);
        float sc    = rstd * __ldg(bn_w + tid);
        sc_s[tid] = sc;
        sh_s[tid] = __ldg(bn_b + tid) - mean * sc;
    }
    __syncthreads();
    size_t stride = (size_t)gridDim.x * blockDim.x;
    size_t total  = (size_t)Nn * 32;
    for (size_t v = (size_t)blockIdx.x * blockDim.x + tid; v < total; v += stride) {
        int q = (int)(v & 31);
        float4 h = reinterpret_cast<float4*>(out)[v];
        float4 sc = *reinterpret_cast<const float4*>(sc_s + q * 4);
        float4 sh = *reinterpret_cast<const float4*>(sh_s + q * 4);
        h.x = h.x * sc.x + sh.x;
        h.y = h.y * sc.y + sh.y;
        h.z = h.z * sc.z + sh.z;
        h.w = h.w * sc.w + sh.w;
        reinterpret_cast<float4*>(out)[v] = h;
    }
    // cleanup for next replay
    int gid = blockIdx.x * blockDim.x + tid;
    if (gid < Nn) g_cnt[gid] = 0;
}

// ---------------------------------------------------------------------------
extern "C" void kernel_launch(void* const* d_in, const int* in_sizes, int n_in,
                              void* d_out, int out_size) {
    const float* x   = (const float*)d_in[0];
    const int*   ei  = (const int*)d_in[1];
    const float* ea  = (const float*)d_in[2];
    const float* W1  = (const float*)d_in[3];
    const float* b1  = (const float*)d_in[4];
    const float* W2  = (const float*)d_in[5];
    const float* b2  = (const float*)d_in[6];
    const float* bnw = (const float*)d_in[7];
    const float* bnb = (const float*)d_in[8];
    float* out = (float*)d_out;

    hist_kernel<<<2 + (E / 4 + 255) / 256, 256>>>(ei, W1, W2);  // (1) pack+hist
    scan_kernel<<<SCAN_G, SCAN_B>>>();                          // (2)
    scatter_kernel<<<(E + 255) / 256, 256>>>(ei);               // (3) + cleanup
    aggregate_kernel<<<(Nn * 32 + 255) / 256, 256>>>(x, ea);    // (4) <- ncu window

    int smem_bytes = (4096 * 2 + 8192 * 2 + 256) * 4;           // 99,328 B
    cudaFuncSetAttribute(mlp_tc, cudaFuncAttributeMaxDynamicSharedMemorySize, smem_bytes);
    int grid = (Nn + 63) / 64;
    mlp_tc<<<grid, 256, smem_bytes>>>(x, b1, nullptr, 0);       // (5)
    mlp_tc<<<grid, 256, smem_bytes>>>(x, b2, out, 1);           // (6)

    bn_kernel<<<2048, 256>>>(out, bnw, bnb);                    // (7)
}

// round 16
// speedup vs baseline: 1.1088x; 1.0605x over previous
#include <cuda_runtime.h>
#include <cuda_bf16.h>
#include <cstdint>

// Problem constants
constexpr int Nn = 50000;
constexpr int D  = 128;
constexpr int E  = 800000;
constexpr int SCAN_B = 512;
constexpr int SCAN_G = (Nn + SCAN_B - 1) / SCAN_B;   // 98

// Scratch (static device globals; zero-initialized at module load, and each
// graph replay restores the zeroed state it needs before exiting).
__device__ float g_aggr[(size_t)Nn * D];   // holds h = x + aggr
__device__ float g_stats[2 * D];
__device__ int   g_cnt[Nn];
__device__ int   g_start[Nn];
__device__ int   g_cur[Nn];
__device__ int   g_desc[SCAN_G];           // decoupled-lookback descriptors
__device__ uint2 g_perm[E];                // (edge_id, src), sorted by dst
// W1/W2 split bf16 hi/lo, fragment-major for m16n8k16 B-operand
__device__ uint32_t g_Bh[2][8192];
__device__ uint32_t g_Bl[2][8192];

// ---------------------------------------------------------------------------
// hist: blocks 0-1 pack W1/W2; blocks 2+ dst histogram (4 edges/thread).
// ---------------------------------------------------------------------------
__global__ void hist_kernel(const int* __restrict__ ei,
                            const float* __restrict__ W1,
                            const float* __restrict__ W2) {
    if (blockIdx.x < 2) {
        const float* W = blockIdx.x ? W2 : W1;
        uint32_t* bh = g_Bh[blockIdx.x];
        uint32_t* bl = g_Bl[blockIdx.x];
        for (int i = threadIdx.x; i < 64 * 128; i += blockDim.x) {
            int k2 = i >> 7, c = i & 127, k = k2 * 2;
            float w0 = __ldg(W + (size_t)k * D + c);
            float w1 = __ldg(W + (size_t)(k + 1) * D + c);
            __nv_bfloat16 h0 = __float2bfloat16(w0);
            __nv_bfloat16 h1 = __float2bfloat16(w1);
            __nv_bfloat16 l0 = __float2bfloat16(w0 - __bfloat162float(h0));
            __nv_bfloat16 l1 = __float2bfloat16(w1 - __bfloat162float(h1));
            int kstep = k2 >> 3;
            int n16   = c >> 4;
            int lane  = (c & 7) * 4 + (k2 & 3);
            int slot  = 2 * ((c >> 3) & 1) + ((k2 >> 2) & 1);
            int idx   = ((kstep * 8 + n16) * 32 + lane) * 4 + slot;
            bh[idx] = (uint32_t)__bfloat16_as_ushort(h0) | ((uint32_t)__bfloat16_as_ushort(h1) << 16);
            bl[idx] = (uint32_t)__bfloat16_as_ushort(l0) | ((uint32_t)__bfloat16_as_ushort(l1) << 16);
        }
    } else {
        int v = (blockIdx.x - 2) * blockDim.x + threadIdx.x;
        if (v < E / 4) {
            int4 d4 = __ldg(reinterpret_cast<const int4*>(ei + E) + v);
            atomicAdd(&g_cnt[d4.x], 1);
            atomicAdd(&g_cnt[d4.y], 1);
            atomicAdd(&g_cnt[d4.z], 1);
            atomicAdd(&g_cnt[d4.w], 1);
        }
    }
}

// ---------------------------------------------------------------------------
// Exclusive scan over g_cnt via decoupled lookback.
// ---------------------------------------------------------------------------
__global__ __launch_bounds__(SCAN_B)
void scan_kernel() {
    __shared__ int sm[SCAN_B];
    __shared__ int s_prefix;
    const int b = blockIdx.x;
    const int t = threadIdx.x;
    int i = b * SCAN_B + t;
    int v = (i < Nn) ? g_cnt[i] : 0;
    sm[t] = v;
    __syncthreads();
#pragma unroll
    for (int off = 1; off < SCAN_B; off <<= 1) {
        int tmp = (t >= off) ? sm[t - off] : 0;
        __syncthreads();
        sm[t] += tmp;
        __syncthreads();
    }
    int total = sm[SCAN_B - 1];

    if (b == 0) {
        if (t == 0) {
            atomicExch(&g_desc[0], (total << 2) | 2);
            s_prefix = 0;
        }
    } else {
        if (t == 0) atomicExch(&g_desc[b], (total << 2) | 1);
        if (t < 32) {
            int prefix = 0, offset = 0;
            bool done = false;
            while (!done) {
                int j = b - 1 - offset - t;
                int d;
                if (j >= 0) {
                    do { d = atomicAdd(&g_desc[j], 0); } while ((d & 3) == 0);
                } else {
                    d = 2;
                }
                unsigned mask = __ballot_sync(0xffffffffu, (d & 3) == 2);
                int contrib;
                if (mask) {
                    int firstP = __ffs(mask) - 1;
                    contrib = (t <= firstP) ? (d >> 2) : 0;
                    done = true;
                } else {
                    contrib = d >> 2;
                }
#pragma unroll
                for (int o = 16; o; o >>= 1) contrib += __shfl_xor_sync(0xffffffffu, contrib, o);
                prefix += contrib;
                offset += 32;
            }
            if (t == 0) {
                atomicExch(&g_desc[b], ((prefix + total) << 2) | 2);
                s_prefix = prefix;
            }
        }
    }
    __syncthreads();
    int s = sm[t] - v + s_prefix;
    if (i < Nn) { g_start[i] = s; g_cur[i] = s; }
}

// ---------------------------------------------------------------------------
// Scatter: 1 edge/thread. Block 0 zeroes g_stats + g_desc for this replay.
// ---------------------------------------------------------------------------
__global__ void scatter_kernel(const int* __restrict__ ei) {
    if (blockIdx.x == 0) {
        if (threadIdx.x < 2 * D) g_stats[threadIdx.x] = 0.f;
        if (threadIdx.x < SCAN_G) g_desc[threadIdx.x] = 0;
    }
    int e = blockIdx.x * blockDim.x + threadIdx.x;
    if (e < E) {
        int src = __ldg(ei + e);
        int dst = __ldg(ei + E + e);
        int pos = atomicAdd(&g_cur[dst], 1);
        g_perm[pos] = make_uint2((unsigned)e, (unsigned)src);
    }
}

// ---------------------------------------------------------------------------
// Aggregate: one warp per node. Byte-identical to the 199.8us version.
// ---------------------------------------------------------------------------
__global__ __launch_bounds__(256)
void aggregate_kernel(const float* __restrict__ x, const float* __restrict__ ea) {
    int node = (int)(((size_t)blockIdx.x * blockDim.x + threadIdx.x) >> 5);
    int lane = threadIdx.x & 31;
    if (node >= Nn) return;
    const float4* x4  = reinterpret_cast<const float4*>(x);
    const float4* ea4 = reinterpret_cast<const float4*>(ea);
    float4 acc = __ldg(x4 + (size_t)node * 32 + lane);   // seed with x_i
    int start = g_start[node];
    int cnt   = g_cnt[node];
    for (int base = 0; base < cnt; base += 32) {
        int m = cnt - base; if (m > 32) m = 32;
        uint2 p = make_uint2(0u, 0u);
        if (lane < m) p = __ldg(g_perm + start + base + lane);
        int m4 = m & ~3;
        for (int j = 0; j < m4; j += 4) {
            uint32_t e0 = __shfl_sync(0xffffffffu, p.x, j);
            uint32_t s0 = __shfl_sync(0xffffffffu, p.y, j);
            uint32_t e1 = __shfl_sync(0xffffffffu, p.x, j + 1);
            uint32_t s1 = __shfl_sync(0xffffffffu, p.y, j + 1);
            uint32_t e2 = __shfl_sync(0xffffffffu, p.x, j + 2);
            uint32_t s2 = __shfl_sync(0xffffffffu, p.y, j + 2);
            uint32_t e3 = __shfl_sync(0xffffffffu, p.x, j + 3);
            uint32_t s3 = __shfl_sync(0xffffffffu, p.y, j + 3);
            float4 xa = __ldg(x4 + (size_t)s0 * 32 + lane);
            float4 va = __ldcs(ea4 + (size_t)e0 * 32 + lane);
            float4 xb = __ldg(x4 + (size_t)s1 * 32 + lane);
            float4 vb = __ldcs(ea4 + (size_t)e1 * 32 + lane);
            float4 xc = __ldg(x4 + (size_t)s2 * 32 + lane);
            float4 vc = __ldcs(ea4 + (size_t)e2 * 32 + lane);
            float4 xd = __ldg(x4 + (size_t)s3 * 32 + lane);
            float4 vd = __ldcs(ea4 + (size_t)e3 * 32 + lane);
            acc.x += fmaxf(xa.x + va.x, 0.f); acc.y += fmaxf(xa.y + va.y, 0.f);
            acc.z += fmaxf(xa.z + va.z, 0.f); acc.w += fmaxf(xa.w + va.w, 0.f);
            acc.x += fmaxf(xb.x + vb.x, 0.f); acc.y += fmaxf(xb.y + vb.y, 0.f);
            acc.z += fmaxf(xb.z + vb.z, 0.f); acc.w += fmaxf(xb.w + vb.w, 0.f);
            acc.x += fmaxf(xc.x + vc.x, 0.f); acc.y += fmaxf(xc.y + vc.y, 0.f);
            acc.z += fmaxf(xc.z + vc.z, 0.f); acc.w += fmaxf(xc.w + vc.w, 0.f);
            acc.x += fmaxf(xd.x + vd.x, 0.f); acc.y += fmaxf(xd.y + vd.y, 0.f);
            acc.z += fmaxf(xd.z + vd.z, 0.f); acc.w += fmaxf(xd.w + vd.w, 0.f);
        }
        for (int j = m4; j < m; j++) {
            uint32_t e = __shfl_sync(0xffffffffu, p.x, j);
            uint32_t s = __shfl_sync(0xffffffffu, p.y, j);
            float4 xv = __ldg(x4 + (size_t)s * 32 + lane);
            float4 ev = __ldcs(ea4 + (size_t)e * 32 + lane);
            acc.x += fmaxf(xv.x + ev.x, 0.f);
            acc.y += fmaxf(xv.y + ev.y, 0.f);
            acc.z += fmaxf(xv.z + ev.z, 0.f);
            acc.w += fmaxf(xv.w + ev.w, 0.f);
        }
    }
    *(reinterpret_cast<float4*>(g_aggr) + (size_t)node * 32 + lane) = acc;
}

// ---------------------------------------------------------------------------
// Fused 2-layer MLP: 64x128 tile, 256 threads (2x4 warp grid), 33 KB smem ->
// 2 blocks/SM. B operands read directly from gmem (128 KB total, L1-resident
// after first touch; identical addresses across blocks). GEMM1 -> relu+b1 ->
// T packed back into Ah/Al -> GEMM2 -> out = x + T@W2 + b2 (+ BN stats).
// ---------------------------------------------------------------------------
#define MMA_BF16(d, av, b0, b1) \
    asm volatile("mma.sync.aligned.m16n8k16.row.col.f32.bf16.bf16.f32 " \
                 "{%0,%1,%2,%3},{%4,%5,%6,%7},{%8,%9},{%0,%1,%2,%3};" \
                 : "+f"((d)[0]), "+f"((d)[1]), "+f"((d)[2]), "+f"((d)[3]) \
                 : "r"((av).x), "r"((av).y), "r"((av).z), "r"((av).w), \
                   "r"(b0), "r"(b1))

__global__ __launch_bounds__(256, 2)
void mlp_fused(const float* __restrict__ x, const float* __restrict__ b1,
               const float* __restrict__ b2, float* __restrict__ out) {
    __shared__ __align__(16) uint32_t Ah[4096];
    __shared__ __align__(16) uint32_t Al[4096];
    __shared__ float cs[D], cq[D];
    const int tid = threadIdx.x, wid = tid >> 5, lane = tid & 31;
    const int r0 = blockIdx.x * 64;
    const int wm = wid & 1, wn = wid >> 1;   // 2x4 warp grid, 32x32 per warp
    const int tg = lane >> 2, tc = lane & 3;

    // A = g_aggr (= x + aggr): load + hi/lo split, fragment-major pack
#pragma unroll
    for (int i = tid; i < 2048; i += 256) {
        int r = i >> 5, q = i & 31;
        int gr = r0 + r;
        float4 a = make_float4(0.f, 0.f, 0.f, 0.f);
        if (gr < Nn)
            a = *(reinterpret_cast<const float4*>(g_aggr) + (size_t)gr * 32 + q);
        __nv_bfloat16 h0 = __float2bfloat16(a.x), h1 = __float2bfloat16(a.y);
        __nv_bfloat16 h2 = __float2bfloat16(a.z), h3 = __float2bfloat16(a.w);
        __nv_bfloat16 l0 = __float2bfloat16(a.x - __bfloat162float(h0));
        __nv_bfloat16 l1 = __float2bfloat16(a.y - __bfloat162float(h1));
        __nv_bfloat16 l2 = __float2bfloat16(a.z - __bfloat162float(h2));
        __nv_bfloat16 l3 = __float2bfloat16(a.w - __bfloat162float(h3));
        uint32_t hp0 = (uint32_t)__bfloat16_as_ushort(h0) | ((uint32_t)__bfloat16_as_ushort(h1) << 16);
        uint32_t hp1 = (uint32_t)__bfloat16_as_ushort(h2) | ((uint32_t)__bfloat16_as_ushort(h3) << 16);
        uint32_t lp0 = (uint32_t)__bfloat16_as_ushort(l0) | ((uint32_t)__bfloat16_as_ushort(l1) << 16);
        uint32_t lp1 = (uint32_t)__bfloat16_as_ushort(l2) | ((uint32_t)__bfloat16_as_ushort(l3) << 16);
        int kstep = q >> 2;
        int m16   = r >> 4;
        int l     = (r & 7) * 4 + (q & 1) * 2;
        int s     = ((r >> 3) & 1) + 2 * ((q >> 1) & 1);
        int base  = (kstep * 4 + m16) * 32;
        int i0 = (base + ((l)     ^ kstep)) * 4 + s;
        int i1 = (base + ((l + 1) ^ kstep)) * 4 + s;
        Ah[i0] = hp0; Ah[i1] = hp1;
        Al[i0] = lp0; Al[i1] = lp1;
    }
    if (tid < 128) { cs[tid] = 0.f; cq[tid] = 0.f; }
    __syncthreads();

    float acc[2][2][2][4];

    // ---------------- GEMM1 (B from gmem/L1) ----------------
#pragma unroll
    for (int im = 0; im < 2; im++)
#pragma unroll
        for (int in = 0; in < 2; in++)
#pragma unroll
            for (int j = 0; j < 2; j++)
#pragma unroll
                for (int v = 0; v < 4; v++) acc[im][in][j][v] = 0.f;

#pragma unroll
    for (int ks = 0; ks < 8; ks++) {
        uint4 ahv[2], alv[2], bhv[2], blv[2];
#pragma unroll
        for (int im = 0; im < 2; im++) {
            int idx = ((ks * 4 + wm * 2 + im) * 32 + (lane ^ ks)) * 4;
            ahv[im] = *reinterpret_cast<const uint4*>(Ah + idx);
            alv[im] = *reinterpret_cast<const uint4*>(Al + idx);
        }
#pragma unroll
        for (int in = 0; in < 2; in++) {
            int idx = ((ks * 8 + wn * 2 + in) * 32 + lane) * 4;
            bhv[in] = __ldg(reinterpret_cast<const uint4*>(g_Bh[0] + idx));
            blv[in] = __ldg(reinterpret_cast<const uint4*>(g_Bl[0] + idx));
        }
#pragma unroll
        for (int im = 0; im < 2; im++)
#pragma unroll
            for (int in = 0; in < 2; in++)
#pragma unroll
                for (int j = 0; j < 2; j++) {
                    uint32_t b0h = j ? bhv[in].z : bhv[in].x;
                    uint32_t b1h_ = j ? bhv[in].w : bhv[in].y;
                    uint32_t b0l = j ? blv[in].z : blv[in].x;
                    uint32_t b1l_ = j ? blv[in].w : blv[in].y;
                    MMA_BF16(acc[im][in][j], ahv[im], b0h, b1h_);
                    MMA_BF16(acc[im][in][j], ahv[im], b0l, b1l_);
                    MMA_BF16(acc[im][in][j], alv[im], b0h, b1h_);
                }
    }
    __syncthreads();   // all warps done reading A tiles

    // ---------------- T = relu(acc + b1) -> back into Ah/Al ----------------
    // Index map: kstep=c>>4, m16=r>>4, l=(r&7)*4+((c>>2)&1)*2+((c>>1)&1),
    // s=((r>>3)&1)+2*((c>>3)&1); u32 = cols {c (lo), c+1 (hi)}, c even.
#pragma unroll
    for (int im = 0; im < 2; im++)
#pragma unroll
        for (int rh = 0; rh < 2; rh++) {
            int r = (wm * 2 + im) * 16 + rh * 8 + tg;
#pragma unroll
            for (int in = 0; in < 2; in++)
#pragma unroll
                for (int j = 0; j < 2; j++) {
                    int c = wn * 32 + in * 16 + j * 8 + tc * 2;
                    float2 bb = __ldg(reinterpret_cast<const float2*>(b1 + c));
                    float v0 = fmaxf(acc[im][in][j][rh * 2]     + bb.x, 0.f);
                    float v1 = fmaxf(acc[im][in][j][rh * 2 + 1] + bb.y, 0.f);
                    __nv_bfloat16 h0 = __float2bfloat16(v0), h1 = __float2bfloat16(v1);
                    __nv_bfloat16 l0 = __float2bfloat16(v0 - __bfloat162float(h0));
                    __nv_bfloat16 l1 = __float2bfloat16(v1 - __bfloat162float(h1));
                    int kstep = c >> 4;
                    int m16   = r >> 4;
                    int l     = (r & 7) * 4 + (((c >> 2) & 1) * 2) + ((c >> 1) & 1);
                    int s     = ((r >> 3) & 1) + 2 * ((c >> 3) & 1);
                    int idx   = ((kstep * 4 + m16) * 32 + (l ^ kstep)) * 4 + s;
                    Ah[idx] = (uint32_t)__bfloat16_as_ushort(h0) | ((uint32_t)__bfloat16_as_ushort(h1) << 16);
                    Al[idx] = (uint32_t)__bfloat16_as_ushort(l0) | ((uint32_t)__bfloat16_as_ushort(l1) << 16);
                }
        }
    __syncthreads();

    // ---------------- GEMM2 (B from gmem/L1) ----------------
#pragma unroll
    for (int im = 0; im < 2; im++)
#pragma unroll
        for (int in = 0; in < 2; in++)
#pragma unroll
            for (int j = 0; j < 2; j++)
#pragma unroll
                for (int v = 0; v < 4; v++) acc[im][in][j][v] = 0.f;

#pragma unroll
    for (int ks = 0; ks < 8; ks++) {
        uint4 ahv[2], alv[2], bhv[2], blv[2];
#pragma unroll
        for (int im = 0; im < 2; im++) {
            int idx = ((ks * 4 + wm * 2 + im) * 32 + (lane ^ ks)) * 4;
            ahv[im] = *reinterpret_cast<const uint4*>(Ah + idx);
            alv[im] = *reinterpret_cast<const uint4*>(Al + idx);
        }
#pragma unroll
        for (int in = 0; in < 2; in++) {
            int idx = ((ks * 8 + wn * 2 + in) * 32 + lane) * 4;
            bhv[in] = __ldg(reinterpret_cast<const uint4*>(g_Bh[1] + idx));
            blv[in] = __ldg(reinterpret_cast<const uint4*>(g_Bl[1] + idx));
        }
#pragma unroll
        for (int im = 0; im < 2; im++)
#pragma unroll
            for (int in = 0; in < 2; in++)
#pragma unroll
                for (int j = 0; j < 2; j++) {
                    uint32_t b0h = j ? bhv[in].z : bhv[in].x;
                    uint32_t b1h_ = j ? bhv[in].w : bhv[in].y;
                    uint32_t b0l = j ? blv[in].z : blv[in].x;
                    uint32_t b1l_ = j ? blv[in].w : blv[in].y;
                    MMA_BF16(acc[im][in][j], ahv[im], b0h, b1h_);
                    MMA_BF16(acc[im][in][j], ahv[im], b0l, b1l_);
                    MMA_BF16(acc[im][in][j], alv[im], b0h, b1h_);
                }
    }

    // ---------------- Epilogue: out = x + acc + b2, BN stats ----------------
    float2 bv[2][2];
#pragma unroll
    for (int in = 0; in < 2; in++)
#pragma unroll
        for (int j = 0; j < 2; j++)
            bv[in][j] = __ldg(reinterpret_cast<const float2*>(b2 + wn * 32 + in * 16 + j * 8 + tc * 2));

    float s8[8], q8[8];
#pragma unroll
    for (int u = 0; u < 8; u++) { s8[u] = 0.f; q8[u] = 0.f; }
#pragma unroll
    for (int im = 0; im < 2; im++)
#pragma unroll
        for (int rh = 0; rh < 2; rh++) {
            int gr = r0 + (wm * 2 + im) * 16 + rh * 8 + tg;
            if (gr < Nn) {
                const float* xr = x + (size_t)gr * D;
                float* op = out + (size_t)gr * D;
#pragma unroll
                for (int in = 0; in < 2; in++)
#pragma unroll
                    for (int j = 0; j < 2; j++) {
                        int col = wn * 32 + in * 16 + j * 8 + tc * 2;
                        float2 xv = __ldg(reinterpret_cast<const float2*>(xr + col));
                        float v0 = acc[im][in][j][rh * 2]     + bv[in][j].x + xv.x;
                        float v1 = acc[im][in][j][rh * 2 + 1] + bv[in][j].y + xv.y;
                        int ci = in * 4 + j * 2;
                        s8[ci] += v0;     q8[ci] += v0 * v0;
                        s8[ci + 1] += v1; q8[ci + 1] += v1 * v1;
                        *reinterpret_cast<float2*>(op + col) = make_float2(v0, v1);
                    }
            }
        }
#pragma unroll
    for (int in = 0; in < 2; in++)
#pragma unroll
        for (int j = 0; j < 2; j++)
#pragma unroll
            for (int h = 0; h < 2; h++) {
                int col = wn * 32 + in * 16 + j * 8 + tc * 2 + h;
                int ci = in * 4 + j * 2 + h;
                atomicAdd(&cs[col], s8[ci]);
                atomicAdd(&cq[col], q8[ci]);
            }
    __syncthreads();
    if (tid < 128) {
        atomicAdd(&g_stats[tid],     cs[tid]);
        atomicAdd(&g_stats[D + tid], cq[tid]);
    }
}

// ---------------------------------------------------------------------------
// BN: scale/shift from stats, in-place apply, then zero g_cnt for next replay.
// ---------------------------------------------------------------------------
__global__ void bn_kernel(float* __restrict__ out,
                          const float* __restrict__ bn_w,
                          const float* __restrict__ bn_b) {
    __shared__ float sc_s[D], sh_s[D];
    int tid = threadIdx.x;
    if (tid < D) {
        float inv_n = 1.f / (float)Nn;
        float mean  = g_stats[tid] * inv_n;
        float var   = g_stats[D + tid] * inv_n - mean * mean;
        float rstd  = rsqrtf(var + 1e-5f);
        float sc    = rstd * __ldg(bn_w + tid);
        sc_s[tid] = sc;
        sh_s[tid] = __ldg(bn_b + tid) - mean * sc;
    }
    __syncthreads();
    size_t stride = (size_t)gridDim.x * blockDim.x;
    size_t total  = (size_t)Nn * 32;
    for (size_t v = (size_t)blockIdx.x * blockDim.x + tid; v < total; v += stride) {
        int q = (int)(v & 31);
        float4 h = reinterpret_cast<float4*>(out)[v];
        float4 sc = *reinterpret_cast<const float4*>(sc_s + q * 4);
        float4 sh = *reinterpret_cast<const float4*>(sh_s + q * 4);
        h.x = h.x * sc.x + sh.x;
        h.y = h.y * sc.y + sh.y;
        h.z = h.z * sc.z + sh.z;
        h.w = h.w * sc.w + sh.w;
        reinterpret_cast<float4*>(out)[v] = h;
    }
    // cleanup for next replay
    int gid = blockIdx.x * blockDim.x + tid;
    if (gid < Nn) g_cnt[gid] = 0;
}

// ---------------------------------------------------------------------------
extern "C" void kernel_launch(void* const* d_in, const int* in_sizes, int n_in,
                              void* d_out, int out_size) {
    const float* x   = (const float*)d_in[0];
    const int*   ei  = (const int*)d_in[1];
    const float* ea  = (const float*)d_in[2];
    const float* W1  = (const float*)d_in[3];
    const float* b1  = (const float*)d_in[4];
    const float* W2  = (const float*)d_in[5];
    const float* b2  = (const float*)d_in[6];
    const float* bnw = (const float*)d_in[7];
    const float* bnb = (const float*)d_in[8];
    float* out = (float*)d_out;

    hist_kernel<<<2 + (E / 4 + 255) / 256, 256>>>(ei, W1, W2);  // (1)
    scan_kernel<<<SCAN_G, SCAN_B>>>();                          // (2)
    scatter_kernel<<<(E + 255) / 256, 256>>>(ei);               // (3)
    aggregate_kernel<<<(Nn * 32 + 255) / 256, 256>>>(x, ea);    // (4)
    mlp_fused<<<(Nn + 63) / 64, 256>>>(x, b1, b2, out);         // (5)
    bn_kernel<<<2048, 256>>>(out, bnw, bnb);                    // (6)
}

// round 17
// speedup vs baseline: 1.1166x; 1.0070x over previous
#include <cuda_runtime.h>
#include <cuda_bf16.h>
#include <cstdint>

// Problem constants
constexpr int Nn = 50000;
constexpr int D  = 128;
constexpr int E  = 800000;
constexpr int SCAN_B = 512;
constexpr int SCAN_G = (Nn + SCAN_B - 1) / SCAN_B;   // 98

// Scratch (static device globals; zero-initialized at module load, and each
// graph replay restores the zeroed state it needs before exiting).
__device__ float g_aggr[(size_t)Nn * D];   // holds h = x + aggr
__device__ float g_stats[2 * D];
__device__ int   g_cnt[Nn];
__device__ int   g_start[Nn];
__device__ int   g_rank[E];                // within-bucket rank per edge (from hist)
__device__ int   g_desc[SCAN_G];           // decoupled-lookback descriptors
__device__ uint2 g_perm[E];                // (edge_id, src), sorted by dst
// W1/W2 split bf16 hi/lo, fragment-major for m16n8k16 B-operand
__device__ uint32_t g_Bh[2][8192];
__device__ uint32_t g_Bl[2][8192];

// ---------------------------------------------------------------------------
// hist: blocks 0-1 pack W1/W2; blocks 2+ dst histogram (4 edges/thread).
// The atomicAdd RETURN VALUE is each edge's unique within-bucket rank --
// persisted to g_rank so scatter needs no atomics at all.
// ---------------------------------------------------------------------------
__global__ void hist_kernel(const int* __restrict__ ei,
                            const float* __restrict__ W1,
                            const float* __restrict__ W2) {
    if (blockIdx.x < 2) {
        const float* W = blockIdx.x ? W2 : W1;
        uint32_t* bh = g_Bh[blockIdx.x];
        uint32_t* bl = g_Bl[blockIdx.x];
        for (int i = threadIdx.x; i < 64 * 128; i += blockDim.x) {
            int k2 = i >> 7, c = i & 127, k = k2 * 2;
            float w0 = __ldg(W + (size_t)k * D + c);
            float w1 = __ldg(W + (size_t)(k + 1) * D + c);
            __nv_bfloat16 h0 = __float2bfloat16(w0);
            __nv_bfloat16 h1 = __float2bfloat16(w1);
            __nv_bfloat16 l0 = __float2bfloat16(w0 - __bfloat162float(h0));
            __nv_bfloat16 l1 = __float2bfloat16(w1 - __bfloat162float(h1));
            int kstep = k2 >> 3;
            int n16   = c >> 4;
            int lane  = (c & 7) * 4 + (k2 & 3);
            int slot  = 2 * ((c >> 3) & 1) + ((k2 >> 2) & 1);
            int idx   = ((kstep * 8 + n16) * 32 + lane) * 4 + slot;
            bh[idx] = (uint32_t)__bfloat16_as_ushort(h0) | ((uint32_t)__bfloat16_as_ushort(h1) << 16);
            bl[idx] = (uint32_t)__bfloat16_as_ushort(l0) | ((uint32_t)__bfloat16_as_ushort(l1) << 16);
        }
    } else {
        int v = (blockIdx.x - 2) * blockDim.x + threadIdx.x;
        if (v < E / 4) {
            int4 d4 = __ldg(reinterpret_cast<const int4*>(ei + E) + v);
            int4 r4;
            r4.x = atomicAdd(&g_cnt[d4.x], 1);
            r4.y = atomicAdd(&g_cnt[d4.y], 1);
            r4.z = atomicAdd(&g_cnt[d4.z], 1);
            r4.w = atomicAdd(&g_cnt[d4.w], 1);
            reinterpret_cast<int4*>(g_rank)[v] = r4;
        }
    }
}

// ---------------------------------------------------------------------------
// Exclusive scan over g_cnt via decoupled lookback.
// ---------------------------------------------------------------------------
__global__ __launch_bounds__(SCAN_B)
void scan_kernel() {
    __shared__ int sm[SCAN_B];
    __shared__ int s_prefix;
    const int b = blockIdx.x;
    const int t = threadIdx.x;
    int i = b * SCAN_B + t;
    int v = (i < Nn) ? g_cnt[i] : 0;
    sm[t] = v;
    __syncthreads();
#pragma unroll
    for (int off = 1; off < SCAN_B; off <<= 1) {
        int tmp = (t >= off) ? sm[t - off] : 0;
        __syncthreads();
        sm[t] += tmp;
        __syncthreads();
    }
    int total = sm[SCAN_B - 1];

    if (b == 0) {
        if (t == 0) {
            atomicExch(&g_desc[0], (total << 2) | 2);
            s_prefix = 0;
        }
    } else {
        if (t == 0) atomicExch(&g_desc[b], (total << 2) | 1);
        if (t < 32) {
            int prefix = 0, offset = 0;
            bool done = false;
            while (!done) {
                int j = b - 1 - offset - t;
                int d;
                if (j >= 0) {
                    do { d = atomicAdd(&g_desc[j], 0); } while ((d & 3) == 0);
                } else {
                    d = 2;
                }
                unsigned mask = __ballot_sync(0xffffffffu, (d & 3) == 2);
                int contrib;
                if (mask) {
                    int firstP = __ffs(mask) - 1;
                    contrib = (t <= firstP) ? (d >> 2) : 0;
                    done = true;
                } else {
                    contrib = d >> 2;
                }
#pragma unroll
                for (int o = 16; o; o >>= 1) contrib += __shfl_xor_sync(0xffffffffu, contrib, o);
                prefix += contrib;
                offset += 32;
            }
            if (t == 0) {
                atomicExch(&g_desc[b], ((prefix + total) << 2) | 2);
                s_prefix = prefix;
            }
        }
    }
    __syncthreads();
    int s = sm[t] - v + s_prefix;
    if (i < Nn) g_start[i] = s;
}

// ---------------------------------------------------------------------------
// Scatter: NO atomics -- pos = g_start[dst] + rank[e] (rank from hist).
// Block 0 zeroes g_stats + g_desc for this replay.
// ---------------------------------------------------------------------------
__global__ void scatter_kernel(const int* __restrict__ ei) {
    if (blockIdx.x == 0) {
        if (threadIdx.x < 2 * D) g_stats[threadIdx.x] = 0.f;
        if (threadIdx.x < SCAN_G) g_desc[threadIdx.x] = 0;
    }
    int e = blockIdx.x * blockDim.x + threadIdx.x;
    if (e < E) {
        int src = __ldg(ei + e);
        int dst = __ldg(ei + E + e);
        int pos = __ldg(&g_start[dst]) + g_rank[e];
        g_perm[pos] = make_uint2((unsigned)e, (unsigned)src);
    }
}

// ---------------------------------------------------------------------------
// Aggregate: one warp per node. Byte-identical to the 188.4us version.
// ---------------------------------------------------------------------------
__global__ __launch_bounds__(256)
void aggregate_kernel(const float* __restrict__ x, const float* __restrict__ ea) {
    int node = (int)(((size_t)blockIdx.x * blockDim.x + threadIdx.x) >> 5);
    int lane = threadIdx.x & 31;
    if (node >= Nn) return;
    const float4* x4  = reinterpret_cast<const float4*>(x);
    const float4* ea4 = reinterpret_cast<const float4*>(ea);
    float4 acc = __ldg(x4 + (size_t)node * 32 + lane);   // seed with x_i
    int start = g_start[node];
    int cnt   = g_cnt[node];
    for (int base = 0; base < cnt; base += 32) {
        int m = cnt - base; if (m > 32) m = 32;
        uint2 p = make_uint2(0u, 0u);
        if (lane < m) p = __ldg(g_perm + start + base + lane);
        int m4 = m & ~3;
        for (int j = 0; j < m4; j += 4) {
            uint32_t e0 = __shfl_sync(0xffffffffu, p.x, j);
            uint32_t s0 = __shfl_sync(0xffffffffu, p.y, j);
            uint32_t e1 = __shfl_sync(0xffffffffu, p.x, j + 1);
            uint32_t s1 = __shfl_sync(0xffffffffu, p.y, j + 1);
            uint32_t e2 = __shfl_sync(0xffffffffu, p.x, j + 2);
            uint32_t s2 = __shfl_sync(0xffffffffu, p.y, j + 2);
            uint32_t e3 = __shfl_sync(0xffffffffu, p.x, j + 3);
            uint32_t s3 = __shfl_sync(0xffffffffu, p.y, j + 3);
            float4 xa = __ldg(x4 + (size_t)s0 * 32 + lane);
            float4 va = __ldcs(ea4 + (size_t)e0 * 32 + lane);
            float4 xb = __ldg(x4 + (size_t)s1 * 32 + lane);
            float4 vb = __ldcs(ea4 + (size_t)e1 * 32 + lane);
            float4 xc = __ldg(x4 + (size_t)s2 * 32 + lane);
            float4 vc = __ldcs(ea4 + (size_t)e2 * 32 + lane);
            float4 xd = __ldg(x4 + (size_t)s3 * 32 + lane);
            float4 vd = __ldcs(ea4 + (size_t)e3 * 32 + lane);
            acc.x += fmaxf(xa.x + va.x, 0.f); acc.y += fmaxf(xa.y + va.y, 0.f);
            acc.z += fmaxf(xa.z + va.z, 0.f); acc.w += fmaxf(xa.w + va.w, 0.f);
            acc.x += fmaxf(xb.x + vb.x, 0.f); acc.y += fmaxf(xb.y + vb.y, 0.f);
            acc.z += fmaxf(xb.z + vb.z, 0.f); acc.w += fmaxf(xb.w + vb.w, 0.f);
            acc.x += fmaxf(xc.x + vc.x, 0.f); acc.y += fmaxf(xc.y + vc.y, 0.f);
            acc.z += fmaxf(xc.z + vc.z, 0.f); acc.w += fmaxf(xc.w + vc.w, 0.f);
            acc.x += fmaxf(xd.x + vd.x, 0.f); acc.y += fmaxf(xd.y + vd.y, 0.f);
            acc.z += fmaxf(xd.z + vd.z, 0.f); acc.w += fmaxf(xd.w + vd.w, 0.f);
        }
        for (int j = m4; j < m; j++) {
            uint32_t e = __shfl_sync(0xffffffffu, p.x, j);
            uint32_t s = __shfl_sync(0xffffffffu, p.y, j);
            float4 xv = __ldg(x4 + (size_t)s * 32 + lane);
            float4 ev = __ldcs(ea4 + (size_t)e * 32 + lane);
            acc.x += fmaxf(xv.x + ev.x, 0.f);
            acc.y += fmaxf(xv.y + ev.y, 0.f);
            acc.z += fmaxf(xv.z + ev.z, 0.f);
            acc.w += fmaxf(xv.w + ev.w, 0.f);
        }
    }
    *(reinterpret_cast<float4*>(g_aggr) + (size_t)node * 32 + lane) = acc;
}

// ---------------------------------------------------------------------------
// Fused 2-layer MLP: 64x128 tile, 256 threads (2x4 warp grid), 33 KB smem ->
// 2 blocks/SM. B operands from gmem/L1. Byte-identical to 188.4us version.
// ---------------------------------------------------------------------------
#define MMA_BF16(d, av, b0, b1) \
    asm volatile("mma.sync.aligned.m16n8k16.row.col.f32.bf16.bf16.f32 " \
                 "{%0,%1,%2,%3},{%4,%5,%6,%7},{%8,%9},{%0,%1,%2,%3};" \
                 : "+f"((d)[0]), "+f"((d)[1]), "+f"((d)[2]), "+f"((d)[3]) \
                 : "r"((av).x), "r"((av).y), "r"((av).z), "r"((av).w), \
                   "r"(b0), "r"(b1))

__global__ __launch_bounds__(256, 2)
void mlp_fused(const float* __restrict__ x, const float* __restrict__ b1,
               const float* __restrict__ b2, float* __restrict__ out) {
    __shared__ __align__(16) uint32_t Ah[4096];
    __shared__ __align__(16) uint32_t Al[4096];
    __shared__ float cs[D], cq[D];
    const int tid = threadIdx.x, wid = tid >> 5, lane = tid & 31;
    const int r0 = blockIdx.x * 64;
    const int wm = wid & 1, wn = wid >> 1;
    const int tg = lane >> 2, tc = lane & 3;

#pragma unroll
    for (int i = tid; i < 2048; i += 256) {
        int r = i >> 5, q = i & 31;
        int gr = r0 + r;
        float4 a = make_float4(0.f, 0.f, 0.f, 0.f);
        if (gr < Nn)
            a = *(reinterpret_cast<const float4*>(g_aggr) + (size_t)gr * 32 + q);
        __nv_bfloat16 h0 = __float2bfloat16(a.x), h1 = __float2bfloat16(a.y);
        __nv_bfloat16 h2 = __float2bfloat16(a.z), h3 = __float2bfloat16(a.w);
        __nv_bfloat16 l0 = __float2bfloat16(a.x - __bfloat162float(h0));
        __nv_bfloat16 l1 = __float2bfloat16(a.y - __bfloat162float(h1));
        __nv_bfloat16 l2 = __float2bfloat16(a.z - __bfloat162float(h2));
        __nv_bfloat16 l3 = __float2bfloat16(a.w - __bfloat162float(h3));
        uint32_t hp0 = (uint32_t)__bfloat16_as_ushort(h0) | ((uint32_t)__bfloat16_as_ushort(h1) << 16);
        uint32_t hp1 = (uint32_t)__bfloat16_as_ushort(h2) | ((uint32_t)__bfloat16_as_ushort(h3) << 16);
        uint32_t lp0 = (uint32_t)__bfloat16_as_ushort(l0) | ((uint32_t)__bfloat16_as_ushort(l1) << 16);
        uint32_t lp1 = (uint32_t)__bfloat16_as_ushort(l2) | ((uint32_t)__bfloat16_as_ushort(l3) << 16);
        int kstep = q >> 2;
        int m16   = r >> 4;
        int l     = (r & 7) * 4 + (q & 1) * 2;
        int s     = ((r >> 3) & 1) + 2 * ((q >> 1) & 1);
        int base  = (kstep * 4 + m16) * 32;
        int i0 = (base + ((l)     ^ kstep)) * 4 + s;
        int i1 = (base + ((l + 1) ^ kstep)) * 4 + s;
        Ah[i0] = hp0; Ah[i1] = hp1;
        Al[i0] = lp0; Al[i1] = lp1;
    }
    if (tid < 128) { cs[tid] = 0.f; cq[tid] = 0.f; }
    __syncthreads();

    float acc[2][2][2][4];

    // ---------------- GEMM1 ----------------
#pragma unroll
    for (int im = 0; im < 2; im++)
#pragma unroll
        for (int in = 0; in < 2; in++)
#pragma unroll
            for (int j = 0; j < 2; j++)
#pragma unroll
                for (int v = 0; v < 4; v++) acc[im][in][j][v] = 0.f;

#pragma unroll
    for (int ks = 0; ks < 8; ks++) {
        uint4 ahv[2], alv[2], bhv[2], blv[2];
#pragma unroll
        for (int im = 0; im < 2; im++) {
            int idx = ((ks * 4 + wm * 2 + im) * 32 + (lane ^ ks)) * 4;
            ahv[im] = *reinterpret_cast<const uint4*>(Ah + idx);
            alv[im] = *reinterpret_cast<const uint4*>(Al + idx);
        }
#pragma unroll
        for (int in = 0; in < 2; in++) {
            int idx = ((ks * 8 + wn * 2 + in) * 32 + lane) * 4;
            bhv[in] = __ldg(reinterpret_cast<const uint4*>(g_Bh[0] + idx));
            blv[in] = __ldg(reinterpret_cast<const uint4*>(g_Bl[0] + idx));
        }
#pragma unroll
        for (int im = 0; im < 2; im++)
#pragma unroll
            for (int in = 0; in < 2; in++)
#pragma unroll
                for (int j = 0; j < 2; j++) {
                    uint32_t b0h = j ? bhv[in].z : bhv[in].x;
                    uint32_t b1h_ = j ? bhv[in].w : bhv[in].y;
                    uint32_t b0l = j ? blv[in].z : blv[in].x;
                    uint32_t b1l_ = j ? blv[in].w : blv[in].y;
                    MMA_BF16(acc[im][in][j], ahv[im], b0h, b1h_);
                    MMA_BF16(acc[im][in][j], ahv[im], b0l, b1l_);
                    MMA_BF16(acc[im][in][j], alv[im], b0h, b1h_);
                }
    }
    __syncthreads();

    // ---------------- T = relu(acc + b1) -> back into Ah/Al ----------------
#pragma unroll
    for (int im = 0; im < 2; im++)
#pragma unroll
        for (int rh = 0; rh < 2; rh++) {
            int r = (wm * 2 + im) * 16 + rh * 8 + tg;
#pragma unroll
            for (int in = 0; in < 2; in++)
#pragma unroll
                for (int j = 0; j < 2; j++) {
                    int c = wn * 32 + in * 16 + j * 8 + tc * 2;
                    float2 bb = __ldg(reinterpret_cast<const float2*>(b1 + c));
                    float v0 = fmaxf(acc[im][in][j][rh * 2]     + bb.x, 0.f);
                    float v1 = fmaxf(acc[im][in][j][rh * 2 + 1] + bb.y, 0.f);
                    __nv_bfloat16 h0 = __float2bfloat16(v0), h1 = __float2bfloat16(v1);
                    __nv_bfloat16 l0 = __float2bfloat16(v0 - __bfloat162float(h0));
                    __nv_bfloat16 l1 = __float2bfloat16(v1 - __bfloat162float(h1));
                    int kstep = c >> 4;
                    int m16   = r >> 4;
                    int l     = (r & 7) * 4 + (((c >> 2) & 1) * 2) + ((c >> 1) & 1);
                    int s     = ((r >> 3) & 1) + 2 * ((c >> 3) & 1);
                    int idx   = ((kstep * 4 + m16) * 32 + (l ^ kstep)) * 4 + s;
                    Ah[idx] = (uint32_t)__bfloat16_as_ushort(h0) | ((uint32_t)__bfloat16_as_ushort(h1) << 16);
                    Al[idx] = (uint32_t)__bfloat16_as_ushort(l0) | ((uint32_t)__bfloat16_as_ushort(l1) << 16);
                }
        }
    __syncthreads();

    // ---------------- GEMM2 ----------------
#pragma unroll
    for (int im = 0; im < 2; im++)
#pragma unroll
        for (int in = 0; in < 2; in++)
#pragma unroll
            for (int j = 0; j < 2; j++)
#pragma unroll
                for (int v = 0; v < 4; v++) acc[im][in][j][v] = 0.f;

#pragma unroll
    for (int ks = 0; ks < 8; ks++) {
        uint4 ahv[2], alv[2], bhv[2], blv[2];
#pragma unroll
        for (int im = 0; im < 2; im++) {
            int idx = ((ks * 4 + wm * 2 + im) * 32 + (lane ^ ks)) * 4;
            ahv[im] = *reinterpret_cast<const uint4*>(Ah + idx);
            alv[im] = *reinterpret_cast<const uint4*>(Al + idx);
        }
#pragma unroll
        for (int in = 0; in < 2; in++) {
            int idx = ((ks * 8 + wn * 2 + in) * 32 + lane) * 4;
            bhv[in] = __ldg(reinterpret_cast<const uint4*>(g_Bh[1] + idx));
            blv[in] = __ldg(reinterpret_cast<const uint4*>(g_Bl[1] + idx));
        }
#pragma unroll
        for (int im = 0; im < 2; im++)
#pragma unroll
            for (int in = 0; in < 2; in++)
#pragma unroll
                for (int j = 0; j < 2; j++) {
                    uint32_t b0h = j ? bhv[in].z : bhv[in].x;
                    uint32_t b1h_ = j ? bhv[in].w : bhv[in].y;
                    uint32_t b0l = j ? blv[in].z : blv[in].x;
                    uint32_t b1l_ = j ? blv[in].w : blv[in].y;
                    MMA_BF16(acc[im][in][j], ahv[im], b0h, b1h_);
                    MMA_BF16(acc[im][in][j], ahv[im], b0l, b1l_);
                    MMA_BF16(acc[im][in][j], alv[im], b0h, b1h_);
                }
    }

    // ---------------- Epilogue: out = x + acc + b2, BN stats ----------------
    float2 bv[2][2];
#pragma unroll
    for (int in = 0; in < 2; in++)
#pragma unroll
        for (int j = 0; j < 2; j++)
            bv[in][j] = __ldg(reinterpret_cast<const float2*>(b2 + wn * 32 + in * 16 + j * 8 + tc * 2));

    float s8[8], q8[8];
#pragma unroll
    for (int u = 0; u < 8; u++) { s8[u] = 0.f; q8[u] = 0.f; }
#pragma unroll
    for (int im = 0; im < 2; im++)
#pragma unroll
        for (int rh = 0; rh < 2; rh++) {
            int gr = r0 + (wm * 2 + im) * 16 + rh * 8 + tg;
            if (gr < Nn) {
                const float* xr = x + (size_t)gr * D;
                float* op = out + (size_t)gr * D;
#pragma unroll
                for (int in = 0; in < 2; in++)
#pragma unroll
                    for (int j = 0; j < 2; j++) {
                        int col = wn * 32 + in * 16 + j * 8 + tc * 2;
                        float2 xv = __ldg(reinterpret_cast<const float2*>(xr + col));
                        float v0 = acc[im][in][j][rh * 2]     + bv[in][j].x + xv.x;
                        float v1 = acc[im][in][j][rh * 2 + 1] + bv[in][j].y + xv.y;
                        int ci = in * 4 + j * 2;
                        s8[ci] += v0;     q8[ci] += v0 * v0;
                        s8[ci + 1] += v1; q8[ci + 1] += v1 * v1;
                        *reinterpret_cast<float2*>(op + col) = make_float2(v0, v1);
                    }
            }
        }
#pragma unroll
    for (int in = 0; in < 2; in++)
#pragma unroll
        for (int j = 0; j < 2; j++)
#pragma unroll
            for (int h = 0; h < 2; h++) {
                int col = wn * 32 + in * 16 + j * 8 + tc * 2 + h;
                int ci = in * 4 + j * 2 + h;
                atomicAdd(&cs[col], s8[ci]);
                atomicAdd(&cq[col], q8[ci]);
            }
    __syncthreads();
    if (tid < 128) {
        atomicAdd(&g_stats[tid],     cs[tid]);
        atomicAdd(&g_stats[D + tid], cq[tid]);
    }
}

// ---------------------------------------------------------------------------
// BN: scale/shift from stats, in-place apply, then zero g_cnt for next replay.
// ---------------------------------------------------------------------------
__global__ void bn_kernel(float* __restrict__ out,
                          const float* __restrict__ bn_w,
                          const float* __restrict__ bn_b) {
    __shared__ float sc_s[D], sh_s[D];
    int tid = threadIdx.x;
    if (tid < D) {
        float inv_n = 1.f / (float)Nn;
        float mean  = g_stats[tid] * inv_n;
        float var   = g_stats[D + tid] * inv_n - mean * mean;
        float rstd  = rsqrtf(var + 1e-5f);
        float sc    = rstd * __ldg(bn_w + tid);
        sc_s[tid] = sc;
        sh_s[tid] = __ldg(bn_b + tid) - mean * sc;
    }
    __syncthreads();
    size_t stride = (size_t)gridDim.x * blockDim.x;
    size_t total  = (size_t)Nn * 32;
    for (size_t v = (size_t)blockIdx.x * blockDim.x + tid; v < total; v += stride) {
        int q = (int)(v & 31);
        float4 h = reinterpret_cast<float4*>(out)[v];
        float4 sc = *reinterpret_cast<const float4*>(sc_s + q * 4);
        float4 sh = *reinterpret_cast<const float4*>(sh_s + q * 4);
        h.x = h.x * sc.x + sh.x;
        h.y = h.y * sc.y + sh.y;
        h.z = h.z * sc.z + sh.z;
        h.w = h.w * sc.w + sh.w;
        reinterpret_cast<float4*>(out)[v] = h;
    }
    // cleanup for next replay
    int gid = blockIdx.x * blockDim.x + tid;
    if (gid < Nn) g_cnt[gid] = 0;
}

// ---------------------------------------------------------------------------
extern "C" void kernel_launch(void* const* d_in, const int* in_sizes, int n_in,
                              void* d_out, int out_size) {
    const float* x   = (const float*)d_in[0];
    const int*   ei  = (const int*)d_in[1];
    const float* ea  = (const float*)d_in[2];
    const float* W1  = (const float*)d_in[3];
    const float* b1  = (const float*)d_in[4];
    const float* W2  = (const float*)d_in[5];
    const float* b2  = (const float*)d_in[6];
    const float* bnw = (const float*)d_in[7];
    const float* bnb = (const float*)d_in[8];
    float* out = (float*)d_out;

    hist_kernel<<<2 + (E / 4 + 255) / 256, 256>>>(ei, W1, W2);  // (1)
    scan_kernel<<<SCAN_G, SCAN_B>>>();                          // (2)
    scatter_kernel<<<(E + 255) / 256, 256>>>(ei);               // (3)
    aggregate_kernel<<<(Nn * 32 + 255) / 256, 256>>>(x, ea);    // (4) <- ncu window
    mlp_fused<<<(Nn + 63) / 64, 256>>>(x, b1, b2, out);         // (5)
    bn_kernel<<<2048, 256>>>(out, bnw, bnb);                    // (6)
}